// round 5
// baseline (speedup 1.0000x reference)
#include <cuda_runtime.h>
#include <math.h>

#define NP    8192
#define INC   256
#define SCC   64
#define OUTC  256
#define KPN   15
#define AGG_PTS 16
#define KNN_TPB 64

// ---------------- scratch (__device__ globals, no allocations) ----------------
__device__ __align__(256) float  g_h   [2 * NP * SCC];               // 4 MB
__device__ __align__(256) int    g_idx [2 * NP * 32];                // 2 MB
__device__ __align__(256) int    g_cnt [2 * NP];
__device__ __align__(256) float  g_h2  [2 * NP * SCC];               // 4 MB
__device__ __align__(256) float  g_part[2 * 2 * 32 * OUTC];
__device__ __align__(256) float  g_mu  [2 * OUTC];
__device__ __align__(256) float  g_rstd[2 * OUTC];
// spatial grid (8x8x8 = 512 cells per cloud)
__device__ __align__(256) int    g_cellcnt  [2 * 512];
__device__ __align__(256) int    g_fill     [2 * 512];
__device__ __align__(256) int    g_cellstart[2 * 513];
__device__ __align__(256) float4 g_sorted   [2 * NP];   // xyz + original index (bits)

// ---------------- 128x64 tiled fp32 GEMM, double-buffered ----------------
#define GEMM_SMEM (2 * (32 * 132 + 32 * 64) * 4)   // 50176 B dynamic

__global__ __launch_bounds__(256) void gemm_k(
    const float* __restrict__ A0, const float* __restrict__ A1,
    const float* __restrict__ B,  const float* __restrict__ bias,
    float* __restrict__ C, int M, int N, int K, size_t strideC)
{
    extern __shared__ float smem_g[];
    float (*As)[32][132] = (float (*)[32][132])smem_g;
    float (*Bs)[32][64]  = (float (*)[32][64])(smem_g + 2 * 32 * 132);

    const float* A = blockIdx.z ? A1 : A0;
    float* Cp = C + (size_t)blockIdx.z * strideC;

    int tid = threadIdx.x;
    int tx = tid & 15;
    int ty = tid >> 4;
    int row0 = blockIdx.y * 128, col0 = blockIdx.x * 64;

    float acc[8][4];
#pragma unroll
    for (int m = 0; m < 8; m++)
#pragma unroll
        for (int n = 0; n < 4; n++) acc[m][n] = 0.f;

    float4 a_reg[4], b_reg[2];
    int ar[4], ac[4], br[2], bc[2];
#pragma unroll
    for (int pass = 0; pass < 4; pass++) {
        int idx = tid + pass * 256;
        ar[pass] = idx >> 3; ac[pass] = (idx & 7) * 4;
    }
#pragma unroll
    for (int pass = 0; pass < 2; pass++) {
        int idx = tid + pass * 256;
        br[pass] = idx >> 4; bc[pass] = (idx & 15) * 4;
    }

    const int KT = K >> 5;

#pragma unroll
    for (int pass = 0; pass < 4; pass++)
        a_reg[pass] = *reinterpret_cast<const float4*>(&A[(size_t)(row0 + ar[pass]) * K + ac[pass]]);
#pragma unroll
    for (int pass = 0; pass < 2; pass++)
        b_reg[pass] = *reinterpret_cast<const float4*>(&B[(size_t)br[pass] * N + col0 + bc[pass]]);
#pragma unroll
    for (int pass = 0; pass < 4; pass++) {
        As[0][ac[pass] + 0][ar[pass]] = a_reg[pass].x;
        As[0][ac[pass] + 1][ar[pass]] = a_reg[pass].y;
        As[0][ac[pass] + 2][ar[pass]] = a_reg[pass].z;
        As[0][ac[pass] + 3][ar[pass]] = a_reg[pass].w;
    }
#pragma unroll
    for (int pass = 0; pass < 2; pass++)
        *reinterpret_cast<float4*>(&Bs[0][br[pass]][bc[pass]]) = b_reg[pass];
    __syncthreads();

    for (int kt = 0; kt < KT; kt++) {
        int cur = kt & 1;
        int k0n = (kt + 1) << 5;
        if (kt + 1 < KT) {
#pragma unroll
            for (int pass = 0; pass < 4; pass++)
                a_reg[pass] = *reinterpret_cast<const float4*>(
                    &A[(size_t)(row0 + ar[pass]) * K + k0n + ac[pass]]);
#pragma unroll
            for (int pass = 0; pass < 2; pass++)
                b_reg[pass] = *reinterpret_cast<const float4*>(
                    &B[(size_t)(k0n + br[pass]) * N + col0 + bc[pass]]);
        }
#pragma unroll
        for (int k = 0; k < 32; k++) {
            float4 a0 = *reinterpret_cast<const float4*>(&As[cur][k][ty * 8]);
            float4 a1 = *reinterpret_cast<const float4*>(&As[cur][k][ty * 8 + 4]);
            float4 b  = *reinterpret_cast<const float4*>(&Bs[cur][k][tx * 4]);
            acc[0][0] += a0.x * b.x; acc[0][1] += a0.x * b.y; acc[0][2] += a0.x * b.z; acc[0][3] += a0.x * b.w;
            acc[1][0] += a0.y * b.x; acc[1][1] += a0.y * b.y; acc[1][2] += a0.y * b.z; acc[1][3] += a0.y * b.w;
            acc[2][0] += a0.z * b.x; acc[2][1] += a0.z * b.y; acc[2][2] += a0.z * b.z; acc[2][3] += a0.z * b.w;
            acc[3][0] += a0.w * b.x; acc[3][1] += a0.w * b.y; acc[3][2] += a0.w * b.z; acc[3][3] += a0.w * b.w;
            acc[4][0] += a1.x * b.x; acc[4][1] += a1.x * b.y; acc[4][2] += a1.x * b.z; acc[4][3] += a1.x * b.w;
            acc[5][0] += a1.y * b.x; acc[5][1] += a1.y * b.y; acc[5][2] += a1.y * b.z; acc[5][3] += a1.y * b.w;
            acc[6][0] += a1.z * b.x; acc[6][1] += a1.z * b.y; acc[6][2] += a1.z * b.z; acc[6][3] += a1.z * b.w;
            acc[7][0] += a1.w * b.x; acc[7][1] += a1.w * b.y; acc[7][2] += a1.w * b.z; acc[7][3] += a1.w * b.w;
        }
        if (kt + 1 < KT) {
            int nxt = (kt + 1) & 1;
#pragma unroll
            for (int pass = 0; pass < 4; pass++) {
                As[nxt][ac[pass] + 0][ar[pass]] = a_reg[pass].x;
                As[nxt][ac[pass] + 1][ar[pass]] = a_reg[pass].y;
                As[nxt][ac[pass] + 2][ar[pass]] = a_reg[pass].z;
                As[nxt][ac[pass] + 3][ar[pass]] = a_reg[pass].w;
            }
#pragma unroll
            for (int pass = 0; pass < 2; pass++)
                *reinterpret_cast<float4*>(&Bs[nxt][br[pass]][bc[pass]]) = b_reg[pass];
            __syncthreads();
        }
    }

    float bv0 = 0.f, bv1 = 0.f, bv2 = 0.f, bv3 = 0.f;
    if (bias) {
        bv0 = bias[col0 + tx * 4 + 0];
        bv1 = bias[col0 + tx * 4 + 1];
        bv2 = bias[col0 + tx * 4 + 2];
        bv3 = bias[col0 + tx * 4 + 3];
    }
#pragma unroll
    for (int m = 0; m < 8; m++) {
        float4 v;
        v.x = acc[m][0] + bv0; v.y = acc[m][1] + bv1;
        v.z = acc[m][2] + bv2; v.w = acc[m][3] + bv3;
        *reinterpret_cast<float4*>(&Cp[(size_t)(row0 + ty * 8 + m) * N + col0 + tx * 4]) = v;
    }
}

// ---------------- spatial grid build ----------------
__device__ __forceinline__ int cell_of(float x, float y, float z) {
    int cx = (int)(x * 8.0f); cx = cx < 0 ? 0 : (cx > 7 ? 7 : cx);
    int cy = (int)(y * 8.0f); cy = cy < 0 ? 0 : (cy > 7 ? 7 : cy);
    int cz = (int)(z * 8.0f); cz = cz < 0 ? 0 : (cz > 7 ? 7 : cz);
    return (cz * 8 + cy) * 8 + cx;
}

__global__ __launch_bounds__(256) void grid_hist(
    const float* __restrict__ c0, const float* __restrict__ c1, int* __restrict__ cnt)
{
    int i = blockIdx.x * 256 + threadIdx.x;
    int cl = i >> 13, p = i & (NP - 1);
    const float* c = cl ? c1 : c0;
    int cell = cell_of(c[3 * p], c[3 * p + 1], c[3 * p + 2]);
    atomicAdd(&cnt[cl * 512 + cell], 1);
}

__global__ __launch_bounds__(512) void grid_scan(
    const int* __restrict__ cnt, int* __restrict__ start)
{
    __shared__ int s[512];
    int cl = blockIdx.x, t = threadIdx.x;
    s[t] = cnt[cl * 512 + t];
    __syncthreads();
#pragma unroll
    for (int off = 1; off < 512; off <<= 1) {
        int v = (t >= off) ? s[t - off] : 0;
        __syncthreads();
        s[t] += v;
        __syncthreads();
    }
    start[cl * 513 + t + 1] = s[t];
    if (t == 0) start[cl * 513] = 0;
}

__global__ __launch_bounds__(256) void grid_scatter(
    const float* __restrict__ c0, const float* __restrict__ c1,
    const int* __restrict__ start, int* __restrict__ fill, float4* __restrict__ sorted)
{
    int i = blockIdx.x * 256 + threadIdx.x;
    int cl = i >> 13, p = i & (NP - 1);
    const float* c = cl ? c1 : c0;
    float x = c[3 * p], y = c[3 * p + 1], z = c[3 * p + 2];
    int cell = cell_of(x, y, z);
    int pos = start[cl * 513 + cell] + atomicAdd(&fill[cl * 512 + cell], 1);
    sorted[cl * NP + pos] = make_float4(x, y, z, __int_as_float(p));
}

// ---------------- kNN via grid: streaming radius-filtered top-32 ----------------
// 64-thread blocks, 256 blocks total -> all SMs busy, fine-grain tail.
__global__ __launch_bounds__(KNN_TPB) void knn_grid(
    const float* __restrict__ c0, const float* __restrict__ c1,
    const int* __restrict__ start, const float4* __restrict__ sorted,
    int* __restrict__ out_idx, int* __restrict__ out_cnt)
{
    extern __shared__ char smraw[];
    float* smd = (float*)smraw;                        // 64*33 floats
    int*   smi = (int*)(smraw + KNN_TPB * 33 * 4);     // 64*33 ints

    int cl = blockIdx.y;
    const float* coords = cl ? c1 : c0;
    int tid = threadIdx.x;
    int q = blockIdx.x * KNN_TPB + tid;

    float qx = coords[3 * q], qy = coords[3 * q + 1], qz = coords[3 * q + 2];
    const float R2 = 0.0144f;

    int cx = (int)(qx * 8.0f); cx = cx < 0 ? 0 : (cx > 7 ? 7 : cx);
    int cy = (int)(qy * 8.0f); cy = cy < 0 ? 0 : (cy > 7 ? 7 : cy);
    int cz = (int)(qz * 8.0f); cz = cz < 0 ? 0 : (cz > 7 ? 7 : cz);
    int xlo = cx > 0 ? cx - 1 : 0, xhi = cx < 7 ? cx + 1 : 7;
    int ylo = cy > 0 ? cy - 1 : 0, yhi = cy < 7 ? cy + 1 : 7;
    int zlo = cz > 0 ? cz - 1 : 0, zhi = cz < 7 ? cz + 1 : 7;

    float* md = smd + tid * 33;
    int*   mi = smi + tid * 33;
    int keep = 0;
    float cm = 0.f; int ca = 0;
    const int* st = start + cl * 513;
    const float4* srt = sorted + (size_t)cl * NP;

    for (int z = zlo; z <= zhi; z++)
        for (int y = ylo; y <= yhi; y++) {
            int rowcell = (z * 8 + y) * 8;
            int jb = st[rowcell + xlo];
            int je = st[rowcell + xhi + 1];
            for (int j = jb; j < je; j++) {
                float4 pc = srt[j];
                float dx = __fsub_rn(qx, pc.x);
                float dy = __fsub_rn(qy, pc.y);
                float dz = __fsub_rn(qz, pc.z);
                float d2 = __fadd_rn(__fadd_rn(__fmul_rn(dx, dx), __fmul_rn(dy, dy)),
                                     __fmul_rn(dz, dz));
                if (d2 <= R2) {
                    if (keep < 32) {
                        md[keep] = d2; mi[keep] = __float_as_int(pc.w); keep++;
                        if (keep == 32) {
                            cm = md[0]; ca = 0;
#pragma unroll
                            for (int s = 1; s < 32; s++) { float v = md[s]; if (v > cm) { cm = v; ca = s; } }
                        }
                    } else if (d2 < cm) {
                        md[ca] = d2; mi[ca] = __float_as_int(pc.w);
                        cm = md[0]; ca = 0;
#pragma unroll
                        for (int s = 1; s < 32; s++) { float v = md[s]; if (v > cm) { cm = v; ca = s; } }
                    }
                }
            }
        }

    int* oi = out_idx + ((size_t)cl * NP + q) * 32;
    for (int s = 0; s < 32; s++) oi[s] = (s < keep) ? mi[s] : 0;
    out_cnt[cl * NP + q] = keep;
}

// ---------------- FUSED: KPConv aggregate + W_kp contraction ----------------
// Per block: 16 points. Stage A builds agg[16][960] in smem (influence-weighted
// neighbor features); Stage B does [16x960]@[960x64] with W_kp streamed through
// L2 (240 KB, chip-resident). Kills the 60 MB g_agg HBM round-trip entirely.
#define AGG_ROW 968   // 960 + 8 pad: breaks bank alignment between pt rows
#define AGG_SMEM ((AGG_PTS * AGG_ROW + AGG_PTS * 32 * KPN + AGG_PTS * 32 * 3 + 48 + AGG_PTS * 32 + AGG_PTS) * 4)

__global__ __launch_bounds__(256) void agg_gemm_kernel(
    const float* __restrict__ c0, const float* __restrict__ c1,
    const int* __restrict__ idx, const int* __restrict__ cntArr,
    const float* __restrict__ h, const float* __restrict__ kpts,
    const float* __restrict__ Wkp, float* __restrict__ h2)
{
    extern __shared__ float sm[];
    float* s_agg  = sm;                                   // [16][968]
    float* s_infl = s_agg + AGG_PTS * AGG_ROW;            // [16][32][15]
    float* s_rel  = s_infl + AGG_PTS * 32 * KPN;          // [16][32][3]
    float* s_kp   = s_rel + AGG_PTS * 32 * 3;             // [48]
    int*   s_idx  = (int*)(s_kp + 48);                    // [16][32]
    int*   s_cnt  = s_idx + AGG_PTS * 32;                 // [16]

    int cl = blockIdx.y;
    const float* coords = cl ? c1 : c0;
    int p0 = blockIdx.x * AGG_PTS;
    int tid = threadIdx.x;
    size_t qbase = (size_t)cl * NP + p0;

    if (tid < KPN * 3) s_kp[tid] = kpts[tid];
    if (tid < AGG_PTS) s_cnt[tid] = cntArr[qbase + tid];
#pragma unroll
    for (int s = 0; s < 2; s++) {
        int i = tid + s * 256;            // 512 (pt,k) pairs
        int pt = i >> 5, k = i & 31;
        s_idx[pt * 32 + k] = idx[(qbase + pt) * 32 + k];
    }
    __syncthreads();

#pragma unroll
    for (int s = 0; s < 2; s++) {
        int i = tid + s * 256;
        int pt = i >> 5, k = i & 31;
        int j = s_idx[pt * 32 + k], n = p0 + pt;
        s_rel[(pt * 32 + k) * 3 + 0] = __fsub_rn(coords[3 * j],     coords[3 * n]);
        s_rel[(pt * 32 + k) * 3 + 1] = __fsub_rn(coords[3 * j + 1], coords[3 * n + 1]);
        s_rel[(pt * 32 + k) * 3 + 2] = __fsub_rn(coords[3 * j + 2], coords[3 * n + 2]);
    }
    __syncthreads();

#pragma unroll
    for (int s = 0; s < 2; s++) {
        int i = tid + s * 256;
        int pt = i >> 5, k = i & 31;
        float rx = s_rel[(pt * 32 + k) * 3 + 0];
        float ry = s_rel[(pt * 32 + k) * 3 + 1];
        float rz = s_rel[(pt * 32 + k) * 3 + 2];
        bool valid = k < s_cnt[pt];
#pragma unroll
        for (int p = 0; p < KPN; p++) {
            float dx = rx - s_kp[p * 3 + 0];
            float dy = ry - s_kp[p * 3 + 1];
            float dz = rz - s_kp[p * 3 + 2];
            float dist = sqrtf(dx * dx + dy * dy + dz * dz);
            float w = fmaxf(1.0f - dist * (1.0f / 0.096f), 0.0f);
            s_infl[(pt * 32 + k) * KPN + p] = valid ? w : 0.0f;
        }
    }
    __syncthreads();

    // -------- Stage A: agg into smem --------
    {
        int pt = tid >> 4;
        int c4 = (tid & 15) << 2;
        const float* hcl = h + (size_t)cl * NP * SCC;

        float acc[KPN][4];
#pragma unroll
        for (int p = 0; p < KPN; p++)
#pragma unroll
            for (int d = 0; d < 4; d++) acc[p][d] = 0.f;

        float4 hv = *reinterpret_cast<const float4*>(&hcl[(size_t)s_idx[pt * 32] * SCC + c4]);
#pragma unroll
        for (int k = 0; k < 32; k++) {
            float4 nxt;
            if (k < 31)
                nxt = *reinterpret_cast<const float4*>(&hcl[(size_t)s_idx[pt * 32 + k + 1] * SCC + c4]);
            const float* wf = &s_infl[(pt * 32 + k) * KPN];
#pragma unroll
            for (int p = 0; p < KPN; p++) {
                float w = wf[p];
                acc[p][0] += w * hv.x; acc[p][1] += w * hv.y;
                acc[p][2] += w * hv.z; acc[p][3] += w * hv.w;
            }
            hv = nxt;
        }

        float* ar = s_agg + pt * AGG_ROW + c4;
#pragma unroll
        for (int p = 0; p < KPN; p++) {
            float4 v; v.x = acc[p][0]; v.y = acc[p][1]; v.z = acc[p][2]; v.w = acc[p][3];
            *reinterpret_cast<float4*>(&ar[p * SCC]) = v;
        }
    }
    __syncthreads();

    // -------- Stage B: h2[16][64] = s_agg[16][960] @ Wkp[960][64] --------
    {
        int pt = tid >> 4;
        int d4 = (tid & 15) << 2;
        const float* arow = s_agg + pt * AGG_ROW;
        float ox = 0.f, oy = 0.f, oz = 0.f, ow = 0.f;

        for (int k0 = 0; k0 < KPN * SCC; k0 += 8) {
            float4 a0 = *reinterpret_cast<const float4*>(arow + k0);
            float4 a1 = *reinterpret_cast<const float4*>(arow + k0 + 4);
            float4 w0 = *reinterpret_cast<const float4*>(&Wkp[(size_t)(k0 + 0) * SCC + d4]);
            float4 w1 = *reinterpret_cast<const float4*>(&Wkp[(size_t)(k0 + 1) * SCC + d4]);
            float4 w2 = *reinterpret_cast<const float4*>(&Wkp[(size_t)(k0 + 2) * SCC + d4]);
            float4 w3 = *reinterpret_cast<const float4*>(&Wkp[(size_t)(k0 + 3) * SCC + d4]);
            float4 w4 = *reinterpret_cast<const float4*>(&Wkp[(size_t)(k0 + 4) * SCC + d4]);
            float4 w5 = *reinterpret_cast<const float4*>(&Wkp[(size_t)(k0 + 5) * SCC + d4]);
            float4 w6 = *reinterpret_cast<const float4*>(&Wkp[(size_t)(k0 + 6) * SCC + d4]);
            float4 w7 = *reinterpret_cast<const float4*>(&Wkp[(size_t)(k0 + 7) * SCC + d4]);
            ox += a0.x * w0.x; oy += a0.x * w0.y; oz += a0.x * w0.z; ow += a0.x * w0.w;
            ox += a0.y * w1.x; oy += a0.y * w1.y; oz += a0.y * w1.z; ow += a0.y * w1.w;
            ox += a0.z * w2.x; oy += a0.z * w2.y; oz += a0.z * w2.z; ow += a0.z * w2.w;
            ox += a0.w * w3.x; oy += a0.w * w3.y; oz += a0.w * w3.z; ow += a0.w * w3.w;
            ox += a1.x * w4.x; oy += a1.x * w4.y; oz += a1.x * w4.z; ow += a1.x * w4.w;
            ox += a1.y * w5.x; oy += a1.y * w5.y; oz += a1.y * w5.z; ow += a1.y * w5.w;
            ox += a1.z * w6.x; oy += a1.z * w6.y; oz += a1.z * w6.z; ow += a1.z * w6.w;
            ox += a1.w * w7.x; oy += a1.w * w7.y; oz += a1.w * w7.z; ow += a1.w * w7.w;
        }
        float4 v; v.x = ox; v.y = oy; v.z = oz; v.w = ow;
        *reinterpret_cast<float4*>(&h2[(qbase + pt) * SCC + d4]) = v;
    }
}

// ---------------- batch norm (deterministic two-pass) + leaky relu ----------------
__global__ __launch_bounds__(256) void bn_partial(const float* __restrict__ y,
                                                  float* __restrict__ part)
{
    int cl = blockIdx.y, b = blockIdx.x, ch = threadIdx.x;
    const float* p = y + (size_t)cl * NP * OUTC + (size_t)b * 256 * OUTC + ch;
    float s = 0.f, s2 = 0.f;
    for (int r = 0; r < 256; r++) {
        float v = p[(size_t)r * OUTC];
        s += v; s2 += v * v;
    }
    float* pp = part + (size_t)cl * 2 * 32 * OUTC;
    pp[b * OUTC + ch] = s;
    pp[32 * OUTC + b * OUTC + ch] = s2;
}

__global__ __launch_bounds__(256) void bn_final(const float* __restrict__ part,
                                                float* __restrict__ mu,
                                                float* __restrict__ rstd)
{
    int cl = blockIdx.x, ch = threadIdx.x;
    const float* pp = part + (size_t)cl * 2 * 32 * OUTC;
    float s = 0.f, s2 = 0.f;
    for (int b = 0; b < 32; b++) {
        s  += pp[b * OUTC + ch];
        s2 += pp[32 * OUTC + b * OUTC + ch];
    }
    float m = s * (1.0f / 8192.0f);
    float v = s2 * (1.0f / 8192.0f) - m * m;
    v = v < 0.f ? 0.f : v;
    mu[cl * OUTC + ch]   = m;
    rstd[cl * OUTC + ch] = rsqrtf(v + 1e-5f);
}

__global__ __launch_bounds__(256) void bn_apply(float* __restrict__ y,
                                                const float* __restrict__ mu,
                                                const float* __restrict__ rstd,
                                                const float* __restrict__ gamma,
                                                const float* __restrict__ beta)
{
    size_t i = (size_t)blockIdx.x * blockDim.x + threadIdx.x;
    int ch = (int)(i & (OUTC - 1));
    int cl = (int)(i >> 21);
    float v = y[i];
    float t = gamma[ch] * (v - mu[cl * OUTC + ch]) * rstd[cl * OUTC + ch] + beta[ch];
    y[i] = t > 0.f ? t : 0.1f * t;
}

// ---------------- launch ----------------
extern "C" void kernel_launch(void* const* d_in, const int* in_sizes, int n_in,
                              void* d_out, int out_size)
{
    const float* src    = (const float*)d_in[0];
    const float* tgt    = (const float*)d_in[1];
    const float* src_c  = (const float*)d_in[2];
    const float* tgt_c  = (const float*)d_in[3];
    const float* W_in   = (const float*)d_in[4];
    const float* b_in   = (const float*)d_in[5];
    const float* kpts   = (const float*)d_in[6];
    const float* W_kp   = (const float*)d_in[7];
    const float* W_out  = (const float*)d_in[8];
    const float* b_out  = (const float*)d_in[9];
    const float* gamma  = (const float*)d_in[10];
    const float* beta   = (const float*)d_in[11];
    float* out = (float*)d_out;

    void* p;
    cudaGetSymbolAddress(&p, g_h);        float*  hP    = (float*)p;
    cudaGetSymbolAddress(&p, g_idx);      int*    idxP  = (int*)p;
    cudaGetSymbolAddress(&p, g_cnt);      int*    cntP  = (int*)p;
    cudaGetSymbolAddress(&p, g_h2);       float*  h2P   = (float*)p;
    cudaGetSymbolAddress(&p, g_part);     float*  partP = (float*)p;
    cudaGetSymbolAddress(&p, g_mu);       float*  muP   = (float*)p;
    cudaGetSymbolAddress(&p, g_rstd);     float*  rstdP = (float*)p;
    cudaGetSymbolAddress(&p, g_cellcnt);  int*    ccntP = (int*)p;
    cudaGetSymbolAddress(&p, g_fill);     int*    fillP = (int*)p;
    cudaGetSymbolAddress(&p, g_cellstart);int*    cstP  = (int*)p;
    cudaGetSymbolAddress(&p, g_sorted);   float4* srtP  = (float4*)p;

    const int KNN_SMEM = KNN_TPB * 33 * 8;   // 16896 B
    cudaFuncSetAttribute(knn_grid, cudaFuncAttributeMaxDynamicSharedMemorySize, KNN_SMEM);
    cudaFuncSetAttribute(gemm_k, cudaFuncAttributeMaxDynamicSharedMemorySize, GEMM_SMEM);
    cudaFuncSetAttribute(agg_gemm_kernel, cudaFuncAttributeMaxDynamicSharedMemorySize, AGG_SMEM);

    // --- spatial grid build (both clouds) ---
    cudaMemsetAsync(ccntP, 0, 2 * 512 * sizeof(int));
    cudaMemsetAsync(fillP, 0, 2 * 512 * sizeof(int));
    grid_hist<<<64, 256>>>(src_c, tgt_c, ccntP);
    grid_scan<<<2, 512>>>(ccntP, cstP);
    grid_scatter<<<64, 256>>>(src_c, tgt_c, cstP, fillP, srtP);

    // 1) h = x @ W_in + b_in
    gemm_k<<<dim3(1, 64, 2), 256, GEMM_SMEM>>>(src, tgt, W_in, b_in, hP,
                                               NP, SCC, INC, (size_t)NP * SCC);

    // 2) grid-accelerated radius-filtered top-32
    knn_grid<<<dim3(NP / KNN_TPB, 2), KNN_TPB, KNN_SMEM>>>(src_c, tgt_c, cstP, srtP,
                                                           idxP, cntP);

    // 3+4) fused KPConv aggregate + W_kp contraction -> h2
    agg_gemm_kernel<<<dim3(NP / AGG_PTS, 2), 256, AGG_SMEM>>>(
        src_c, tgt_c, idxP, cntP, hP, kpts, W_kp, h2P);

    // 5) y = h2 @ W_out + b_out -> directly into d_out
    gemm_k<<<dim3(4, 64, 2), 256, GEMM_SMEM>>>(h2P, h2P + (size_t)NP * SCC, W_out, b_out,
                                               out, NP, OUTC, SCC, (size_t)NP * OUTC);

    // 6) batch norm (train-mode stats) + leaky relu, in place on d_out
    bn_partial<<<dim3(32, 2), 256>>>(out, partP);
    bn_final<<<2, 256>>>(partP, muP, rstdP);
    bn_apply<<<(2 * NP * OUTC) / 256, 256>>>(out, muP, rstdP, gamma, beta);

    // 7) coords pass-through
    cudaMemcpyAsync(out + (size_t)2 * NP * OUTC, src_c, NP * 3 * sizeof(float),
                    cudaMemcpyDeviceToDevice);
    cudaMemcpyAsync(out + (size_t)2 * NP * OUTC + NP * 3, tgt_c, NP * 3 * sizeof(float),
                    cudaMemcpyDeviceToDevice);
}

// round 6
// speedup vs baseline: 1.2216x; 1.2216x over previous
#include <cuda_runtime.h>
#include <cuda_fp16.h>
#include <math.h>

#define NP    8192
#define INC   256
#define SCC   64
#define OUTC  256
#define KPN   15
#define AGG_PTS 16
#define KNN_TPB 64

// ---------------- scratch (__device__ globals, no allocations) ----------------
__device__ __align__(256) float  g_h   [2 * NP * SCC];                 // 4 MB
__device__ __align__(256) int    g_idx [2 * NP * 32];                  // 2 MB
__device__ __align__(256) int    g_cnt [2 * NP];
__device__ __align__(256) __half g_agg [(size_t)2 * NP * KPN * SCC];   // 30 MB (fp16)
__device__ __align__(256) float  g_h2  [2 * NP * SCC];                 // 4 MB
__device__ __align__(256) float  g_part[2 * 2 * 32 * OUTC];
__device__ __align__(256) float  g_mu  [2 * OUTC];
__device__ __align__(256) float  g_rstd[2 * OUTC];
// spatial grid (8x8x8 = 512 cells per cloud)
__device__ __align__(256) int    g_cellcnt  [2 * 512];
__device__ __align__(256) int    g_fill     [2 * 512];
__device__ __align__(256) int    g_cellstart[2 * 513];
__device__ __align__(256) float4 g_sorted   [2 * NP];   // xyz + original index (bits)

// ---------------- 128x64 tiled fp32 GEMM, double-buffered ----------------
#define GEMM_SMEM (2 * (32 * 132 + 32 * 64) * 4)   // 50176 B dynamic

__global__ __launch_bounds__(256) void gemm_k(
    const float* __restrict__ A0, const float* __restrict__ A1,
    const float* __restrict__ B,  const float* __restrict__ bias,
    float* __restrict__ C, int M, int N, int K, size_t strideC)
{
    extern __shared__ float smem_g[];
    float (*As)[32][132] = (float (*)[32][132])smem_g;
    float (*Bs)[32][64]  = (float (*)[32][64])(smem_g + 2 * 32 * 132);

    const float* A = blockIdx.z ? A1 : A0;
    float* Cp = C + (size_t)blockIdx.z * strideC;

    int tid = threadIdx.x;
    int tx = tid & 15;
    int ty = tid >> 4;
    int row0 = blockIdx.y * 128, col0 = blockIdx.x * 64;

    float acc[8][4];
#pragma unroll
    for (int m = 0; m < 8; m++)
#pragma unroll
        for (int n = 0; n < 4; n++) acc[m][n] = 0.f;

    float4 a_reg[4], b_reg[2];
    int ar[4], ac[4], br[2], bc[2];
#pragma unroll
    for (int pass = 0; pass < 4; pass++) {
        int idx = tid + pass * 256;
        ar[pass] = idx >> 3; ac[pass] = (idx & 7) * 4;
    }
#pragma unroll
    for (int pass = 0; pass < 2; pass++) {
        int idx = tid + pass * 256;
        br[pass] = idx >> 4; bc[pass] = (idx & 15) * 4;
    }

    const int KT = K >> 5;

#pragma unroll
    for (int pass = 0; pass < 4; pass++)
        a_reg[pass] = *reinterpret_cast<const float4*>(&A[(size_t)(row0 + ar[pass]) * K + ac[pass]]);
#pragma unroll
    for (int pass = 0; pass < 2; pass++)
        b_reg[pass] = *reinterpret_cast<const float4*>(&B[(size_t)br[pass] * N + col0 + bc[pass]]);
#pragma unroll
    for (int pass = 0; pass < 4; pass++) {
        As[0][ac[pass] + 0][ar[pass]] = a_reg[pass].x;
        As[0][ac[pass] + 1][ar[pass]] = a_reg[pass].y;
        As[0][ac[pass] + 2][ar[pass]] = a_reg[pass].z;
        As[0][ac[pass] + 3][ar[pass]] = a_reg[pass].w;
    }
#pragma unroll
    for (int pass = 0; pass < 2; pass++)
        *reinterpret_cast<float4*>(&Bs[0][br[pass]][bc[pass]]) = b_reg[pass];
    __syncthreads();

    for (int kt = 0; kt < KT; kt++) {
        int cur = kt & 1;
        int k0n = (kt + 1) << 5;
        if (kt + 1 < KT) {
#pragma unroll
            for (int pass = 0; pass < 4; pass++)
                a_reg[pass] = *reinterpret_cast<const float4*>(
                    &A[(size_t)(row0 + ar[pass]) * K + k0n + ac[pass]]);
#pragma unroll
            for (int pass = 0; pass < 2; pass++)
                b_reg[pass] = *reinterpret_cast<const float4*>(
                    &B[(size_t)(k0n + br[pass]) * N + col0 + bc[pass]]);
        }
#pragma unroll
        for (int k = 0; k < 32; k++) {
            float4 a0 = *reinterpret_cast<const float4*>(&As[cur][k][ty * 8]);
            float4 a1 = *reinterpret_cast<const float4*>(&As[cur][k][ty * 8 + 4]);
            float4 b  = *reinterpret_cast<const float4*>(&Bs[cur][k][tx * 4]);
            acc[0][0] += a0.x * b.x; acc[0][1] += a0.x * b.y; acc[0][2] += a0.x * b.z; acc[0][3] += a0.x * b.w;
            acc[1][0] += a0.y * b.x; acc[1][1] += a0.y * b.y; acc[1][2] += a0.y * b.z; acc[1][3] += a0.y * b.w;
            acc[2][0] += a0.z * b.x; acc[2][1] += a0.z * b.y; acc[2][2] += a0.z * b.z; acc[2][3] += a0.z * b.w;
            acc[3][0] += a0.w * b.x; acc[3][1] += a0.w * b.y; acc[3][2] += a0.w * b.z; acc[3][3] += a0.w * b.w;
            acc[4][0] += a1.x * b.x; acc[4][1] += a1.x * b.y; acc[4][2] += a1.x * b.z; acc[4][3] += a1.x * b.w;
            acc[5][0] += a1.y * b.x; acc[5][1] += a1.y * b.y; acc[5][2] += a1.y * b.z; acc[5][3] += a1.y * b.w;
            acc[6][0] += a1.z * b.x; acc[6][1] += a1.z * b.y; acc[6][2] += a1.z * b.z; acc[6][3] += a1.z * b.w;
            acc[7][0] += a1.w * b.x; acc[7][1] += a1.w * b.y; acc[7][2] += a1.w * b.z; acc[7][3] += a1.w * b.w;
        }
        if (kt + 1 < KT) {
            int nxt = (kt + 1) & 1;
#pragma unroll
            for (int pass = 0; pass < 4; pass++) {
                As[nxt][ac[pass] + 0][ar[pass]] = a_reg[pass].x;
                As[nxt][ac[pass] + 1][ar[pass]] = a_reg[pass].y;
                As[nxt][ac[pass] + 2][ar[pass]] = a_reg[pass].z;
                As[nxt][ac[pass] + 3][ar[pass]] = a_reg[pass].w;
            }
#pragma unroll
            for (int pass = 0; pass < 2; pass++)
                *reinterpret_cast<float4*>(&Bs[nxt][br[pass]][bc[pass]]) = b_reg[pass];
            __syncthreads();
        }
    }

    float bv0 = 0.f, bv1 = 0.f, bv2 = 0.f, bv3 = 0.f;
    if (bias) {
        bv0 = bias[col0 + tx * 4 + 0];
        bv1 = bias[col0 + tx * 4 + 1];
        bv2 = bias[col0 + tx * 4 + 2];
        bv3 = bias[col0 + tx * 4 + 3];
    }
#pragma unroll
    for (int m = 0; m < 8; m++) {
        float4 v;
        v.x = acc[m][0] + bv0; v.y = acc[m][1] + bv1;
        v.z = acc[m][2] + bv2; v.w = acc[m][3] + bv3;
        *reinterpret_cast<float4*>(&Cp[(size_t)(row0 + ty * 8 + m) * N + col0 + tx * 4]) = v;
    }
}

// ---------------- same GEMM but A is fp16 (for the K=960 contraction) ----------------
__global__ __launch_bounds__(256) void gemm_h(
    const __half* __restrict__ A0, const __half* __restrict__ A1,
    const float* __restrict__ B, float* __restrict__ C,
    int M, int N, int K, size_t strideC)
{
    extern __shared__ float smem_g[];
    float (*As)[32][132] = (float (*)[32][132])smem_g;
    float (*Bs)[32][64]  = (float (*)[32][64])(smem_g + 2 * 32 * 132);

    const __half* A = blockIdx.z ? A1 : A0;
    float* Cp = C + (size_t)blockIdx.z * strideC;

    int tid = threadIdx.x;
    int tx = tid & 15;
    int ty = tid >> 4;
    int row0 = blockIdx.y * 128, col0 = blockIdx.x * 64;

    float acc[8][4];
#pragma unroll
    for (int m = 0; m < 8; m++)
#pragma unroll
        for (int n = 0; n < 4; n++) acc[m][n] = 0.f;

    // A tile: 128 rows x 32 halfs = 512 chunks of 8 halfs (16 B); 2 passes
    uint4 a_reg[2]; float4 b_reg[2];
    int ar[2], ac[2], br[2], bc[2];
#pragma unroll
    for (int pass = 0; pass < 2; pass++) {
        int idx = tid + pass * 256;
        ar[pass] = idx >> 2; ac[pass] = (idx & 3) * 8;
        br[pass] = idx >> 4; bc[pass] = (idx & 15) * 4;
    }

    const int KT = K >> 5;

#pragma unroll
    for (int pass = 0; pass < 2; pass++) {
        a_reg[pass] = *reinterpret_cast<const uint4*>(&A[(size_t)(row0 + ar[pass]) * K + ac[pass]]);
        b_reg[pass] = *reinterpret_cast<const float4*>(&B[(size_t)br[pass] * N + col0 + bc[pass]]);
    }
#pragma unroll
    for (int pass = 0; pass < 2; pass++) {
        const __half2* hp = reinterpret_cast<const __half2*>(&a_reg[pass]);
#pragma unroll
        for (int w = 0; w < 4; w++) {
            float2 f = __half22float2(hp[w]);
            As[0][ac[pass] + 2 * w + 0][ar[pass]] = f.x;
            As[0][ac[pass] + 2 * w + 1][ar[pass]] = f.y;
        }
        *reinterpret_cast<float4*>(&Bs[0][br[pass]][bc[pass]]) = b_reg[pass];
    }
    __syncthreads();

    for (int kt = 0; kt < KT; kt++) {
        int cur = kt & 1;
        int k0n = (kt + 1) << 5;
        if (kt + 1 < KT) {
#pragma unroll
            for (int pass = 0; pass < 2; pass++) {
                a_reg[pass] = *reinterpret_cast<const uint4*>(
                    &A[(size_t)(row0 + ar[pass]) * K + k0n + ac[pass]]);
                b_reg[pass] = *reinterpret_cast<const float4*>(
                    &B[(size_t)(k0n + br[pass]) * N + col0 + bc[pass]]);
            }
        }
#pragma unroll
        for (int k = 0; k < 32; k++) {
            float4 a0 = *reinterpret_cast<const float4*>(&As[cur][k][ty * 8]);
            float4 a1 = *reinterpret_cast<const float4*>(&As[cur][k][ty * 8 + 4]);
            float4 b  = *reinterpret_cast<const float4*>(&Bs[cur][k][tx * 4]);
            acc[0][0] += a0.x * b.x; acc[0][1] += a0.x * b.y; acc[0][2] += a0.x * b.z; acc[0][3] += a0.x * b.w;
            acc[1][0] += a0.y * b.x; acc[1][1] += a0.y * b.y; acc[1][2] += a0.y * b.z; acc[1][3] += a0.y * b.w;
            acc[2][0] += a0.z * b.x; acc[2][1] += a0.z * b.y; acc[2][2] += a0.z * b.z; acc[2][3] += a0.z * b.w;
            acc[3][0] += a0.w * b.x; acc[3][1] += a0.w * b.y; acc[3][2] += a0.w * b.z; acc[3][3] += a0.w * b.w;
            acc[4][0] += a1.x * b.x; acc[4][1] += a1.x * b.y; acc[4][2] += a1.x * b.z; acc[4][3] += a1.x * b.w;
            acc[5][0] += a1.y * b.x; acc[5][1] += a1.y * b.y; acc[5][2] += a1.y * b.z; acc[5][3] += a1.y * b.w;
            acc[6][0] += a1.z * b.x; acc[6][1] += a1.z * b.y; acc[6][2] += a1.z * b.z; acc[6][3] += a1.z * b.w;
            acc[7][0] += a1.w * b.x; acc[7][1] += a1.w * b.y; acc[7][2] += a1.w * b.z; acc[7][3] += a1.w * b.w;
        }
        if (kt + 1 < KT) {
            int nxt = (kt + 1) & 1;
#pragma unroll
            for (int pass = 0; pass < 2; pass++) {
                const __half2* hp = reinterpret_cast<const __half2*>(&a_reg[pass]);
#pragma unroll
                for (int w = 0; w < 4; w++) {
                    float2 f = __half22float2(hp[w]);
                    As[nxt][ac[pass] + 2 * w + 0][ar[pass]] = f.x;
                    As[nxt][ac[pass] + 2 * w + 1][ar[pass]] = f.y;
                }
                *reinterpret_cast<float4*>(&Bs[nxt][br[pass]][bc[pass]]) = b_reg[pass];
            }
            __syncthreads();
        }
    }

#pragma unroll
    for (int m = 0; m < 8; m++) {
        float4 v;
        v.x = acc[m][0]; v.y = acc[m][1]; v.z = acc[m][2]; v.w = acc[m][3];
        *reinterpret_cast<float4*>(&Cp[(size_t)(row0 + ty * 8 + m) * N + col0 + tx * 4]) = v;
    }
}

// ---------------- spatial grid build ----------------
__device__ __forceinline__ int cell_of(float x, float y, float z) {
    int cx = (int)(x * 8.0f); cx = cx < 0 ? 0 : (cx > 7 ? 7 : cx);
    int cy = (int)(y * 8.0f); cy = cy < 0 ? 0 : (cy > 7 ? 7 : cy);
    int cz = (int)(z * 8.0f); cz = cz < 0 ? 0 : (cz > 7 ? 7 : cz);
    return (cz * 8 + cy) * 8 + cx;
}

__global__ __launch_bounds__(256) void grid_hist(
    const float* __restrict__ c0, const float* __restrict__ c1, int* __restrict__ cnt)
{
    int i = blockIdx.x * 256 + threadIdx.x;
    int cl = i >> 13, p = i & (NP - 1);
    const float* c = cl ? c1 : c0;
    int cell = cell_of(c[3 * p], c[3 * p + 1], c[3 * p + 2]);
    atomicAdd(&cnt[cl * 512 + cell], 1);
}

__global__ __launch_bounds__(512) void grid_scan(
    const int* __restrict__ cnt, int* __restrict__ start)
{
    __shared__ int s[512];
    int cl = blockIdx.x, t = threadIdx.x;
    s[t] = cnt[cl * 512 + t];
    __syncthreads();
#pragma unroll
    for (int off = 1; off < 512; off <<= 1) {
        int v = (t >= off) ? s[t - off] : 0;
        __syncthreads();
        s[t] += v;
        __syncthreads();
    }
    start[cl * 513 + t + 1] = s[t];
    if (t == 0) start[cl * 513] = 0;
}

__global__ __launch_bounds__(256) void grid_scatter(
    const float* __restrict__ c0, const float* __restrict__ c1,
    const int* __restrict__ start, int* __restrict__ fill, float4* __restrict__ sorted)
{
    int i = blockIdx.x * 256 + threadIdx.x;
    int cl = i >> 13, p = i & (NP - 1);
    const float* c = cl ? c1 : c0;
    float x = c[3 * p], y = c[3 * p + 1], z = c[3 * p + 2];
    int cell = cell_of(x, y, z);
    int pos = start[cl * 513 + cell] + atomicAdd(&fill[cl * 512 + cell], 1);
    sorted[cl * NP + pos] = make_float4(x, y, z, __int_as_float(p));
}

// ---------------- kNN via grid: streaming radius-filtered top-32 ----------------
__global__ __launch_bounds__(KNN_TPB) void knn_grid(
    const float* __restrict__ c0, const float* __restrict__ c1,
    const int* __restrict__ start, const float4* __restrict__ sorted,
    int* __restrict__ out_idx, int* __restrict__ out_cnt)
{
    extern __shared__ char smraw[];
    float* smd = (float*)smraw;
    int*   smi = (int*)(smraw + KNN_TPB * 33 * 4);

    int cl = blockIdx.y;
    const float* coords = cl ? c1 : c0;
    int tid = threadIdx.x;
    int q = blockIdx.x * KNN_TPB + tid;

    float qx = coords[3 * q], qy = coords[3 * q + 1], qz = coords[3 * q + 2];
    const float R2 = 0.0144f;

    int cx = (int)(qx * 8.0f); cx = cx < 0 ? 0 : (cx > 7 ? 7 : cx);
    int cy = (int)(qy * 8.0f); cy = cy < 0 ? 0 : (cy > 7 ? 7 : cy);
    int cz = (int)(qz * 8.0f); cz = cz < 0 ? 0 : (cz > 7 ? 7 : cz);
    int xlo = cx > 0 ? cx - 1 : 0, xhi = cx < 7 ? cx + 1 : 7;
    int ylo = cy > 0 ? cy - 1 : 0, yhi = cy < 7 ? cy + 1 : 7;
    int zlo = cz > 0 ? cz - 1 : 0, zhi = cz < 7 ? cz + 1 : 7;

    float* md = smd + tid * 33;
    int*   mi = smi + tid * 33;
    int keep = 0;
    float cm = 0.f; int ca = 0;
    const int* st = start + cl * 513;
    const float4* srt = sorted + (size_t)cl * NP;

    for (int z = zlo; z <= zhi; z++)
        for (int y = ylo; y <= yhi; y++) {
            int rowcell = (z * 8 + y) * 8;
            int jb = st[rowcell + xlo];
            int je = st[rowcell + xhi + 1];
            for (int j = jb; j < je; j++) {
                float4 pc = srt[j];
                float dx = __fsub_rn(qx, pc.x);
                float dy = __fsub_rn(qy, pc.y);
                float dz = __fsub_rn(qz, pc.z);
                float d2 = __fadd_rn(__fadd_rn(__fmul_rn(dx, dx), __fmul_rn(dy, dy)),
                                     __fmul_rn(dz, dz));
                if (d2 <= R2) {
                    if (keep < 32) {
                        md[keep] = d2; mi[keep] = __float_as_int(pc.w); keep++;
                        if (keep == 32) {
                            cm = md[0]; ca = 0;
#pragma unroll
                            for (int s = 1; s < 32; s++) { float v = md[s]; if (v > cm) { cm = v; ca = s; } }
                        }
                    } else if (d2 < cm) {
                        md[ca] = d2; mi[ca] = __float_as_int(pc.w);
                        cm = md[0]; ca = 0;
#pragma unroll
                        for (int s = 1; s < 32; s++) { float v = md[s]; if (v > cm) { cm = v; ca = s; } }
                    }
                }
            }
        }

    int* oi = out_idx + ((size_t)cl * NP + q) * 32;
    for (int s = 0; s < 32; s++) oi[s] = (s < keep) ? mi[s] : 0;
    out_cnt[cl * NP + q] = keep;
}

// ---------------- KPConv aggregate (register-resident, 16 pts/block, fp16 out) ----------------
__global__ __launch_bounds__(256) void agg_kernel(
    const float* __restrict__ c0, const float* __restrict__ c1,
    const int* __restrict__ idx, const int* __restrict__ cntArr,
    const float* __restrict__ h, const float* __restrict__ kpts,
    __half* __restrict__ agg)
{
    __shared__ float s_infl[AGG_PTS][32][KPN];
    __shared__ int   s_idx[AGG_PTS][32];
    __shared__ float s_rel[AGG_PTS][32][3];
    __shared__ float s_kp[KPN][3];
    __shared__ int   s_cnt[AGG_PTS];

    int cl = blockIdx.y;
    const float* coords = cl ? c1 : c0;
    int p0 = blockIdx.x * AGG_PTS;
    int tid = threadIdx.x;
    size_t qbase = (size_t)cl * NP + p0;

    if (tid < KPN * 3) s_kp[tid / 3][tid % 3] = kpts[tid];
    if (tid < AGG_PTS) s_cnt[tid] = cntArr[qbase + tid];
#pragma unroll
    for (int s = 0; s < 2; s++) {
        int i = tid + s * 256;
        int pt = i >> 5, k = i & 31;
        s_idx[pt][k] = idx[(qbase + pt) * 32 + k];
    }
    __syncthreads();

#pragma unroll
    for (int s = 0; s < 2; s++) {
        int i = tid + s * 256;
        int pt = i >> 5, k = i & 31;
        int j = s_idx[pt][k], n = p0 + pt;
        s_rel[pt][k][0] = __fsub_rn(coords[3 * j],     coords[3 * n]);
        s_rel[pt][k][1] = __fsub_rn(coords[3 * j + 1], coords[3 * n + 1]);
        s_rel[pt][k][2] = __fsub_rn(coords[3 * j + 2], coords[3 * n + 2]);
    }
    __syncthreads();

#pragma unroll
    for (int s = 0; s < 2; s++) {
        int i = tid + s * 256;
        int pt = i >> 5, k = i & 31;
        float rx = s_rel[pt][k][0], ry = s_rel[pt][k][1], rz = s_rel[pt][k][2];
        bool valid = k < s_cnt[pt];
#pragma unroll
        for (int p = 0; p < KPN; p++) {
            float dx = rx - s_kp[p][0];
            float dy = ry - s_kp[p][1];
            float dz = rz - s_kp[p][2];
            float dist = sqrtf(dx * dx + dy * dy + dz * dz);
            float w = fmaxf(1.0f - dist * (1.0f / 0.096f), 0.0f);
            s_infl[pt][k][p] = valid ? w : 0.0f;
        }
    }
    __syncthreads();

    int pt = tid >> 4;
    int c4 = (tid & 15) << 2;
    const float* hcl = h + (size_t)cl * NP * SCC;

    float acc[KPN][4];
#pragma unroll
    for (int p = 0; p < KPN; p++)
#pragma unroll
        for (int d = 0; d < 4; d++) acc[p][d] = 0.f;

    float4 hv = *reinterpret_cast<const float4*>(&hcl[(size_t)s_idx[pt][0] * SCC + c4]);
#pragma unroll
    for (int k = 0; k < 32; k++) {
        float4 nxt;
        if (k < 31)
            nxt = *reinterpret_cast<const float4*>(&hcl[(size_t)s_idx[pt][k + 1] * SCC + c4]);
#pragma unroll
        for (int p = 0; p < KPN; p++) {
            float w = s_infl[pt][k][p];
            acc[p][0] += w * hv.x; acc[p][1] += w * hv.y;
            acc[p][2] += w * hv.z; acc[p][3] += w * hv.w;
        }
        hv = nxt;
    }

    __half* o = agg + (qbase + pt) * (KPN * SCC) + c4;
#pragma unroll
    for (int p = 0; p < KPN; p++) {
        __half2 h01 = __floats2half2_rn(acc[p][0], acc[p][1]);
        __half2 h23 = __floats2half2_rn(acc[p][2], acc[p][3]);
        uint2 pk;
        pk.x = *reinterpret_cast<unsigned int*>(&h01);
        pk.y = *reinterpret_cast<unsigned int*>(&h23);
        *reinterpret_cast<uint2*>(&o[p * SCC]) = pk;
    }
}

// ---------------- batch norm (deterministic two-pass) + leaky relu ----------------
__global__ __launch_bounds__(256) void bn_partial(const float* __restrict__ y,
                                                  float* __restrict__ part)
{
    int cl = blockIdx.y, b = blockIdx.x, ch = threadIdx.x;
    const float* p = y + (size_t)cl * NP * OUTC + (size_t)b * 256 * OUTC + ch;
    float s = 0.f, s2 = 0.f;
    for (int r = 0; r < 256; r++) {
        float v = p[(size_t)r * OUTC];
        s += v; s2 += v * v;
    }
    float* pp = part + (size_t)cl * 2 * 32 * OUTC;
    pp[b * OUTC + ch] = s;
    pp[32 * OUTC + b * OUTC + ch] = s2;
}

__global__ __launch_bounds__(256) void bn_final(const float* __restrict__ part,
                                                float* __restrict__ mu,
                                                float* __restrict__ rstd)
{
    int cl = blockIdx.x, ch = threadIdx.x;
    const float* pp = part + (size_t)cl * 2 * 32 * OUTC;
    float s = 0.f, s2 = 0.f;
    for (int b = 0; b < 32; b++) {
        s  += pp[b * OUTC + ch];
        s2 += pp[32 * OUTC + b * OUTC + ch];
    }
    float m = s * (1.0f / 8192.0f);
    float v = s2 * (1.0f / 8192.0f) - m * m;
    v = v < 0.f ? 0.f : v;
    mu[cl * OUTC + ch]   = m;
    rstd[cl * OUTC + ch] = rsqrtf(v + 1e-5f);
}

__global__ __launch_bounds__(256) void bn_apply(float* __restrict__ y,
                                                const float* __restrict__ mu,
                                                const float* __restrict__ rstd,
                                                const float* __restrict__ gamma,
                                                const float* __restrict__ beta)
{
    size_t i = (size_t)blockIdx.x * blockDim.x + threadIdx.x;
    int ch = (int)(i & (OUTC - 1));
    int cl = (int)(i >> 21);
    float v = y[i];
    float t = gamma[ch] * (v - mu[cl * OUTC + ch]) * rstd[cl * OUTC + ch] + beta[ch];
    y[i] = t > 0.f ? t : 0.1f * t;
}

// ---------------- launch ----------------
extern "C" void kernel_launch(void* const* d_in, const int* in_sizes, int n_in,
                              void* d_out, int out_size)
{
    const float* src    = (const float*)d_in[0];
    const float* tgt    = (const float*)d_in[1];
    const float* src_c  = (const float*)d_in[2];
    const float* tgt_c  = (const float*)d_in[3];
    const float* W_in   = (const float*)d_in[4];
    const float* b_in   = (const float*)d_in[5];
    const float* kpts   = (const float*)d_in[6];
    const float* W_kp   = (const float*)d_in[7];
    const float* W_out  = (const float*)d_in[8];
    const float* b_out  = (const float*)d_in[9];
    const float* gamma  = (const float*)d_in[10];
    const float* beta   = (const float*)d_in[11];
    float* out = (float*)d_out;

    void* p;
    cudaGetSymbolAddress(&p, g_h);        float*  hP    = (float*)p;
    cudaGetSymbolAddress(&p, g_idx);      int*    idxP  = (int*)p;
    cudaGetSymbolAddress(&p, g_cnt);      int*    cntP  = (int*)p;
    cudaGetSymbolAddress(&p, g_agg);      __half* aggP  = (__half*)p;
    cudaGetSymbolAddress(&p, g_h2);       float*  h2P   = (float*)p;
    cudaGetSymbolAddress(&p, g_part);     float*  partP = (float*)p;
    cudaGetSymbolAddress(&p, g_mu);       float*  muP   = (float*)p;
    cudaGetSymbolAddress(&p, g_rstd);     float*  rstdP = (float*)p;
    cudaGetSymbolAddress(&p, g_cellcnt);  int*    ccntP = (int*)p;
    cudaGetSymbolAddress(&p, g_fill);     int*    fillP = (int*)p;
    cudaGetSymbolAddress(&p, g_cellstart);int*    cstP  = (int*)p;
    cudaGetSymbolAddress(&p, g_sorted);   float4* srtP  = (float4*)p;

    const int KNN_SMEM = KNN_TPB * 33 * 8;   // 16896 B
    cudaFuncSetAttribute(knn_grid, cudaFuncAttributeMaxDynamicSharedMemorySize, KNN_SMEM);
    cudaFuncSetAttribute(gemm_k, cudaFuncAttributeMaxDynamicSharedMemorySize, GEMM_SMEM);
    cudaFuncSetAttribute(gemm_h, cudaFuncAttributeMaxDynamicSharedMemorySize, GEMM_SMEM);

    // --- spatial grid build (both clouds) ---
    cudaMemsetAsync(ccntP, 0, 2 * 512 * sizeof(int));
    cudaMemsetAsync(fillP, 0, 2 * 512 * sizeof(int));
    grid_hist<<<64, 256>>>(src_c, tgt_c, ccntP);
    grid_scan<<<2, 512>>>(ccntP, cstP);
    grid_scatter<<<64, 256>>>(src_c, tgt_c, cstP, fillP, srtP);

    // 1) h = x @ W_in + b_in
    gemm_k<<<dim3(1, 64, 2), 256, GEMM_SMEM>>>(src, tgt, W_in, b_in, hP,
                                               NP, SCC, INC, (size_t)NP * SCC);

    // 2) grid-accelerated radius-filtered top-32
    knn_grid<<<dim3(NP / KNN_TPB, 2), KNN_TPB, KNN_SMEM>>>(src_c, tgt_c, cstP, srtP,
                                                           idxP, cntP);

    // 3) KPConv influence-weighted aggregation -> agg [N, 960] (fp16)
    agg_kernel<<<dim3(NP / AGG_PTS, 2), 256>>>(src_c, tgt_c, idxP, cntP, hP, kpts, aggP);

    // 4) h2 = agg @ W_kp  ([8192,960]x[960,64], A in fp16)
    gemm_h<<<dim3(1, 64, 2), 256, GEMM_SMEM>>>(aggP, aggP + (size_t)NP * KPN * SCC, W_kp,
                                               h2P, NP, SCC, KPN * SCC, (size_t)NP * SCC);

    // 5) y = h2 @ W_out + b_out -> directly into d_out
    gemm_k<<<dim3(4, 64, 2), 256, GEMM_SMEM>>>(h2P, h2P + (size_t)NP * SCC, W_out, b_out,
                                               out, NP, OUTC, SCC, (size_t)NP * OUTC);

    // 6) batch norm (train-mode stats) + leaky relu, in place on d_out
    bn_partial<<<dim3(32, 2), 256>>>(out, partP);
    bn_final<<<2, 256>>>(partP, muP, rstdP);
    bn_apply<<<(2 * NP * OUTC) / 256, 256>>>(out, muP, rstdP, gamma, beta);

    // 7) coords pass-through
    cudaMemcpyAsync(out + (size_t)2 * NP * OUTC, src_c, NP * 3 * sizeof(float),
                    cudaMemcpyDeviceToDevice);
    cudaMemcpyAsync(out + (size_t)2 * NP * OUTC + NP * 3, tgt_c, NP * 3 * sizeof(float),
                    cudaMemcpyDeviceToDevice);
}

// round 8
// speedup vs baseline: 1.3523x; 1.1069x over previous
#include <cuda_runtime.h>
#include <cuda_fp16.h>
#include <stdint.h>
#include <math.h>

#define NP    8192
#define INC   256
#define SCC   64
#define OUTC  256
#define KPN   15
#define KDIM  (KPN * SCC)     // 960
#define AGG_PTS 16
#define KNN_TPB 64

// ---------------- scratch (__device__ globals, no allocations) ----------------
__device__ __align__(256) float  g_h   [2 * NP * SCC];                 // 4 MB
__device__ __align__(256) int    g_idx [2 * NP * 32];                  // 2 MB
__device__ __align__(256) int    g_cnt [2 * NP];
__device__ __align__(256) __half g_agg [(size_t)2 * NP * KDIM];        // 30 MB (fp16)
__device__ __align__(256) __half g_wt  [SCC * KDIM];                   // W_kp^T fp16 [64][960]
__device__ __align__(256) float  g_h2  [2 * NP * SCC];                 // 4 MB
__device__ __align__(256) float  g_part[2 * 2 * 64 * OUTC];
__device__ __align__(256) float  g_mu  [2 * OUTC];
__device__ __align__(256) float  g_rstd[2 * OUTC];
// spatial grid (8x8x8 = 512 cells per cloud)
__device__ __align__(256) int    g_cellcnt  [2 * 512];
__device__ __align__(256) int    g_fill     [2 * 512];
__device__ __align__(256) int    g_cellstart[2 * 513];
__device__ __align__(256) float4 g_sorted   [2 * NP];   // xyz + original index (bits)

// ---------------- 128x64 tiled fp32 GEMM, double-buffered, optional BN partials ----------------
#define GEMM_SMEM (2 * (32 * 132 + 32 * 64) * 4)   // 50176 B dynamic

__global__ __launch_bounds__(256) void gemm_k(
    const float* __restrict__ A0, const float* __restrict__ A1,
    const float* __restrict__ B,  const float* __restrict__ bias,
    float* __restrict__ C, int M, int N, int K, size_t strideC,
    float* __restrict__ part)
{
    extern __shared__ float smem_g[];
    float (*As)[32][132] = (float (*)[32][132])smem_g;
    float (*Bs)[32][64]  = (float (*)[32][64])(smem_g + 2 * 32 * 132);

    const float* A = blockIdx.z ? A1 : A0;
    float* Cp = C + (size_t)blockIdx.z * strideC;

    int tid = threadIdx.x;
    int tx = tid & 15;
    int ty = tid >> 4;
    int row0 = blockIdx.y * 128, col0 = blockIdx.x * 64;

    float acc[8][4];
#pragma unroll
    for (int m = 0; m < 8; m++)
#pragma unroll
        for (int n = 0; n < 4; n++) acc[m][n] = 0.f;

    float4 a_reg[4], b_reg[2];
    int ar[4], ac[4], br[2], bc[2];
#pragma unroll
    for (int pass = 0; pass < 4; pass++) {
        int idx = tid + pass * 256;
        ar[pass] = idx >> 3; ac[pass] = (idx & 7) * 4;
    }
#pragma unroll
    for (int pass = 0; pass < 2; pass++) {
        int idx = tid + pass * 256;
        br[pass] = idx >> 4; bc[pass] = (idx & 15) * 4;
    }

    const int KT = K >> 5;

#pragma unroll
    for (int pass = 0; pass < 4; pass++)
        a_reg[pass] = *reinterpret_cast<const float4*>(&A[(size_t)(row0 + ar[pass]) * K + ac[pass]]);
#pragma unroll
    for (int pass = 0; pass < 2; pass++)
        b_reg[pass] = *reinterpret_cast<const float4*>(&B[(size_t)br[pass] * N + col0 + bc[pass]]);
#pragma unroll
    for (int pass = 0; pass < 4; pass++) {
        As[0][ac[pass] + 0][ar[pass]] = a_reg[pass].x;
        As[0][ac[pass] + 1][ar[pass]] = a_reg[pass].y;
        As[0][ac[pass] + 2][ar[pass]] = a_reg[pass].z;
        As[0][ac[pass] + 3][ar[pass]] = a_reg[pass].w;
    }
#pragma unroll
    for (int pass = 0; pass < 2; pass++)
        *reinterpret_cast<float4*>(&Bs[0][br[pass]][bc[pass]]) = b_reg[pass];
    __syncthreads();

    for (int kt = 0; kt < KT; kt++) {
        int cur = kt & 1;
        int k0n = (kt + 1) << 5;
        if (kt + 1 < KT) {
#pragma unroll
            for (int pass = 0; pass < 4; pass++)
                a_reg[pass] = *reinterpret_cast<const float4*>(
                    &A[(size_t)(row0 + ar[pass]) * K + k0n + ac[pass]]);
#pragma unroll
            for (int pass = 0; pass < 2; pass++)
                b_reg[pass] = *reinterpret_cast<const float4*>(
                    &B[(size_t)(k0n + br[pass]) * N + col0 + bc[pass]]);
        }
#pragma unroll
        for (int k = 0; k < 32; k++) {
            float4 a0 = *reinterpret_cast<const float4*>(&As[cur][k][ty * 8]);
            float4 a1 = *reinterpret_cast<const float4*>(&As[cur][k][ty * 8 + 4]);
            float4 b  = *reinterpret_cast<const float4*>(&Bs[cur][k][tx * 4]);
            acc[0][0] += a0.x * b.x; acc[0][1] += a0.x * b.y; acc[0][2] += a0.x * b.z; acc[0][3] += a0.x * b.w;
            acc[1][0] += a0.y * b.x; acc[1][1] += a0.y * b.y; acc[1][2] += a0.y * b.z; acc[1][3] += a0.y * b.w;
            acc[2][0] += a0.z * b.x; acc[2][1] += a0.z * b.y; acc[2][2] += a0.z * b.z; acc[2][3] += a0.z * b.w;
            acc[3][0] += a0.w * b.x; acc[3][1] += a0.w * b.y; acc[3][2] += a0.w * b.z; acc[3][3] += a0.w * b.w;
            acc[4][0] += a1.x * b.x; acc[4][1] += a1.x * b.y; acc[4][2] += a1.x * b.z; acc[4][3] += a1.x * b.w;
            acc[5][0] += a1.y * b.x; acc[5][1] += a1.y * b.y; acc[5][2] += a1.y * b.z; acc[5][3] += a1.y * b.w;
            acc[6][0] += a1.z * b.x; acc[6][1] += a1.z * b.y; acc[6][2] += a1.z * b.z; acc[6][3] += a1.z * b.w;
            acc[7][0] += a1.w * b.x; acc[7][1] += a1.w * b.y; acc[7][2] += a1.w * b.z; acc[7][3] += a1.w * b.w;
        }
        if (kt + 1 < KT) {
            int nxt = (kt + 1) & 1;
#pragma unroll
            for (int pass = 0; pass < 4; pass++) {
                As[nxt][ac[pass] + 0][ar[pass]] = a_reg[pass].x;
                As[nxt][ac[pass] + 1][ar[pass]] = a_reg[pass].y;
                As[nxt][ac[pass] + 2][ar[pass]] = a_reg[pass].z;
                As[nxt][ac[pass] + 3][ar[pass]] = a_reg[pass].w;
            }
#pragma unroll
            for (int pass = 0; pass < 2; pass++)
                *reinterpret_cast<float4*>(&Bs[nxt][br[pass]][bc[pass]]) = b_reg[pass];
            __syncthreads();
        }
    }

    float bv0 = 0.f, bv1 = 0.f, bv2 = 0.f, bv3 = 0.f;
    if (bias) {
        bv0 = bias[col0 + tx * 4 + 0];
        bv1 = bias[col0 + tx * 4 + 1];
        bv2 = bias[col0 + tx * 4 + 2];
        bv3 = bias[col0 + tx * 4 + 3];
    }
    float s0 = 0.f, s1 = 0.f, s2c = 0.f, s3 = 0.f;
    float q0 = 0.f, q1 = 0.f, q2 = 0.f, q3 = 0.f;
#pragma unroll
    for (int m = 0; m < 8; m++) {
        float4 v;
        v.x = acc[m][0] + bv0; v.y = acc[m][1] + bv1;
        v.z = acc[m][2] + bv2; v.w = acc[m][3] + bv3;
        *reinterpret_cast<float4*>(&Cp[(size_t)(row0 + ty * 8 + m) * N + col0 + tx * 4]) = v;
        s0 += v.x; s1 += v.y; s2c += v.z; s3 += v.w;
        q0 += v.x * v.x; q1 += v.y * v.y; q2 += v.z * v.z; q3 += v.w * v.w;
    }

    // BN partial sums (deterministic: per (rowblock, col), serial reduction)
    if (part) {
        __syncthreads();
        float* red = smem_g;            // reuse: [2][16][64]
        red[ty * 64 + tx * 4 + 0] = s0;
        red[ty * 64 + tx * 4 + 1] = s1;
        red[ty * 64 + tx * 4 + 2] = s2c;
        red[ty * 64 + tx * 4 + 3] = s3;
        red[1024 + ty * 64 + tx * 4 + 0] = q0;
        red[1024 + ty * 64 + tx * 4 + 1] = q1;
        red[1024 + ty * 64 + tx * 4 + 2] = q2;
        red[1024 + ty * 64 + tx * 4 + 3] = q3;
        __syncthreads();
        if (tid < 64) {
            float ss = 0.f, qq = 0.f;
#pragma unroll
            for (int t = 0; t < 16; t++) {
                ss += red[t * 64 + tid];
                qq += red[1024 + t * 64 + tid];
            }
            int cl = blockIdx.z;
            int ch = col0 + tid;
            part[((size_t)(cl * 2 + 0) * 64 + blockIdx.y) * OUTC + ch] = ss;
            part[((size_t)(cl * 2 + 1) * 64 + blockIdx.y) * OUTC + ch] = qq;
        }
    }
}

// ---------------- W_kp fp32 [960][64] -> fp16 transposed [64][960] ----------------
__global__ __launch_bounds__(256) void wconv(const float* __restrict__ W,
                                             __half* __restrict__ Wt)
{
    int i = blockIdx.x * 256 + threadIdx.x;   // over 960*64
    int k = i >> 6, n = i & 63;
    Wt[n * KDIM + k] = __float2half_rn(W[i]);
}

// ---------------- HMMA fp16 GEMM: h2 = agg[8192,960] @ Wkp[960,64] ----------------
// mma.sync m16n8k16, fp32 accumulate. Block 128x64, 8 warps (4x2), k-tile 32.
__device__ __forceinline__ void mma16816(float* c, const uint32_t* a, const uint32_t* b) {
    asm volatile(
        "mma.sync.aligned.m16n8k16.row.col.f32.f16.f16.f32 "
        "{%0,%1,%2,%3}, {%4,%5,%6,%7}, {%8,%9}, {%0,%1,%2,%3};\n"
        : "+f"(c[0]), "+f"(c[1]), "+f"(c[2]), "+f"(c[3])
        : "r"(a[0]), "r"(a[1]), "r"(a[2]), "r"(a[3]), "r"(b[0]), "r"(b[1]));
}

__global__ __launch_bounds__(256) void gemm_hmma(
    const __half* __restrict__ A, const __half* __restrict__ Wt,
    float* __restrict__ C)
{
    __shared__ __half As[128][40];   // 80 B rows: 16B-aligned, conflict-spread frags
    __shared__ __half Bs[64][40];

    int cl = blockIdx.y;
    const __half* Ab = A + (size_t)cl * NP * KDIM;
    float* Cb = C + (size_t)cl * NP * SCC;
    int row0 = blockIdx.x * 128;
    int tid = threadIdx.x, lane = tid & 31, warp = tid >> 5;
    int wm = warp >> 1, wn = warp & 1;
    int g = lane >> 2, tig = lane & 3;

    float acc[2][4][4];
#pragma unroll
    for (int am = 0; am < 2; am++)
#pragma unroll
        for (int an = 0; an < 4; an++)
#pragma unroll
            for (int d = 0; d < 4; d++) acc[am][an][d] = 0.f;

    for (int k0 = 0; k0 < KDIM; k0 += 32) {
        // A tile 128x32 halfs: 512 16B chunks
#pragma unroll
        for (int s = 0; s < 2; s++) {
            int ch = tid + s * 256;
            int r = ch >> 2, k8 = (ch & 3) * 8;
            *reinterpret_cast<uint4*>(&As[r][k8]) =
                *reinterpret_cast<const uint4*>(&Ab[(size_t)(row0 + r) * KDIM + k0 + k8]);
        }
        // B tile 64x32 halfs from Wt[n][k]: 256 16B chunks
        {
            int n = tid >> 2, k8 = (tid & 3) * 8;
            *reinterpret_cast<uint4*>(&Bs[n][k8]) =
                *reinterpret_cast<const uint4*>(&Wt[(size_t)n * KDIM + k0 + k8]);
        }
        __syncthreads();

#pragma unroll
        for (int ks = 0; ks < 32; ks += 16) {
            uint32_t a[2][4], b[4][2];
#pragma unroll
            for (int am = 0; am < 2; am++) {
                int r = wm * 32 + am * 16 + g;
                a[am][0] = *reinterpret_cast<const uint32_t*>(&As[r][ks + tig * 2]);
                a[am][1] = *reinterpret_cast<const uint32_t*>(&As[r + 8][ks + tig * 2]);
                a[am][2] = *reinterpret_cast<const uint32_t*>(&As[r][ks + tig * 2 + 8]);
                a[am][3] = *reinterpret_cast<const uint32_t*>(&As[r + 8][ks + tig * 2 + 8]);
            }
#pragma unroll
            for (int an = 0; an < 4; an++) {
                int n = wn * 32 + an * 8 + g;
                b[an][0] = *reinterpret_cast<const uint32_t*>(&Bs[n][ks + tig * 2]);
                b[an][1] = *reinterpret_cast<const uint32_t*>(&Bs[n][ks + tig * 2 + 8]);
            }
#pragma unroll
            for (int am = 0; am < 2; am++)
#pragma unroll
                for (int an = 0; an < 4; an++)
                    mma16816(acc[am][an], a[am], b[an]);
        }
        __syncthreads();
    }

#pragma unroll
    for (int am = 0; am < 2; am++)
#pragma unroll
        for (int an = 0; an < 4; an++) {
            int r = row0 + wm * 32 + am * 16 + g;
            int c = wn * 32 + an * 8 + tig * 2;
            float2 v0; v0.x = acc[am][an][0]; v0.y = acc[am][an][1];
            float2 v1; v1.x = acc[am][an][2]; v1.y = acc[am][an][3];
            *reinterpret_cast<float2*>(&Cb[(size_t)r * SCC + c]) = v0;
            *reinterpret_cast<float2*>(&Cb[(size_t)(r + 8) * SCC + c]) = v1;
        }
}

// ---------------- spatial grid build ----------------
__device__ __forceinline__ int cell_of(float x, float y, float z) {
    int cx = (int)(x * 8.0f); cx = cx < 0 ? 0 : (cx > 7 ? 7 : cx);
    int cy = (int)(y * 8.0f); cy = cy < 0 ? 0 : (cy > 7 ? 7 : cy);
    int cz = (int)(z * 8.0f); cz = cz < 0 ? 0 : (cz > 7 ? 7 : cz);
    return (cz * 8 + cy) * 8 + cx;
}

__global__ __launch_bounds__(256) void grid_hist(
    const float* __restrict__ c0, const float* __restrict__ c1, int* __restrict__ cnt)
{
    int i = blockIdx.x * 256 + threadIdx.x;
    int cl = i >> 13, p = i & (NP - 1);
    const float* c = cl ? c1 : c0;
    int cell = cell_of(c[3 * p], c[3 * p + 1], c[3 * p + 2]);
    atomicAdd(&cnt[cl * 512 + cell], 1);
}

__global__ __launch_bounds__(512) void grid_scan(
    const int* __restrict__ cnt, int* __restrict__ start)
{
    __shared__ int s[512];
    int cl = blockIdx.x, t = threadIdx.x;
    s[t] = cnt[cl * 512 + t];
    __syncthreads();
#pragma unroll
    for (int off = 1; off < 512; off <<= 1) {
        int v = (t >= off) ? s[t - off] : 0;
        __syncthreads();
        s[t] += v;
        __syncthreads();
    }
    start[cl * 513 + t + 1] = s[t];
    if (t == 0) start[cl * 513] = 0;
}

__global__ __launch_bounds__(256) void grid_scatter(
    const float* __restrict__ c0, const float* __restrict__ c1,
    const int* __restrict__ start, int* __restrict__ fill, float4* __restrict__ sorted)
{
    int i = blockIdx.x * 256 + threadIdx.x;
    int cl = i >> 13, p = i & (NP - 1);
    const float* c = cl ? c1 : c0;
    float x = c[3 * p], y = c[3 * p + 1], z = c[3 * p + 2];
    int cell = cell_of(x, y, z);
    int pos = start[cl * 513 + cell] + atomicAdd(&fill[cl * 512 + cell], 1);
    sorted[cl * NP + pos] = make_float4(x, y, z, __int_as_float(p));
}

// ---------------- kNN via grid: streaming radius-filtered top-32 ----------------
__global__ __launch_bounds__(KNN_TPB) void knn_grid(
    const float* __restrict__ c0, const float* __restrict__ c1,
    const int* __restrict__ start, const float4* __restrict__ sorted,
    int* __restrict__ out_idx, int* __restrict__ out_cnt)
{
    extern __shared__ char smraw[];
    float* smd = (float*)smraw;
    int*   smi = (int*)(smraw + KNN_TPB * 33 * 4);

    int cl = blockIdx.y;
    const float* coords = cl ? c1 : c0;
    int tid = threadIdx.x;
    int q = blockIdx.x * KNN_TPB + tid;

    float qx = coords[3 * q], qy = coords[3 * q + 1], qz = coords[3 * q + 2];
    const float R2 = 0.0144f;

    int cx = (int)(qx * 8.0f); cx = cx < 0 ? 0 : (cx > 7 ? 7 : cx);
    int cy = (int)(qy * 8.0f); cy = cy < 0 ? 0 : (cy > 7 ? 7 : cy);
    int cz = (int)(qz * 8.0f); cz = cz < 0 ? 0 : (cz > 7 ? 7 : cz);
    int xlo = cx > 0 ? cx - 1 : 0, xhi = cx < 7 ? cx + 1 : 7;
    int ylo = cy > 0 ? cy - 1 : 0, yhi = cy < 7 ? cy + 1 : 7;
    int zlo = cz > 0 ? cz - 1 : 0, zhi = cz < 7 ? cz + 1 : 7;

    float* md = smd + tid * 33;
    int*   mi = smi + tid * 33;
    int keep = 0;
    float cm = 0.f; int ca = 0;
    const int* st = start + cl * 513;
    const float4* srt = sorted + (size_t)cl * NP;

    for (int z = zlo; z <= zhi; z++)
        for (int y = ylo; y <= yhi; y++) {
            int rowcell = (z * 8 + y) * 8;
            int jb = st[rowcell + xlo];
            int je = st[rowcell + xhi + 1];
            for (int j = jb; j < je; j++) {
                float4 pc = srt[j];
                float dx = __fsub_rn(qx, pc.x);
                float dy = __fsub_rn(qy, pc.y);
                float dz = __fsub_rn(qz, pc.z);
                float d2 = __fadd_rn(__fadd_rn(__fmul_rn(dx, dx), __fmul_rn(dy, dy)),
                                     __fmul_rn(dz, dz));
                if (d2 <= R2) {
                    if (keep < 32) {
                        md[keep] = d2; mi[keep] = __float_as_int(pc.w); keep++;
                        if (keep == 32) {
                            cm = md[0]; ca = 0;
#pragma unroll
                            for (int s = 1; s < 32; s++) { float v = md[s]; if (v > cm) { cm = v; ca = s; } }
                        }
                    } else if (d2 < cm) {
                        md[ca] = d2; mi[ca] = __float_as_int(pc.w);
                        cm = md[0]; ca = 0;
#pragma unroll
                        for (int s = 1; s < 32; s++) { float v = md[s]; if (v > cm) { cm = v; ca = s; } }
                    }
                }
            }
        }

    int* oi = out_idx + ((size_t)cl * NP + q) * 32;
    for (int s = 0; s < 32; s++) oi[s] = (s < keep) ? mi[s] : 0;
    out_cnt[cl * NP + q] = keep;
}

// ---------------- KPConv aggregate (register-resident, 16 pts/block, fp16 out) ----------------
__global__ __launch_bounds__(256) void agg_kernel(
    const float* __restrict__ c0, const float* __restrict__ c1,
    const int* __restrict__ idx, const int* __restrict__ cntArr,
    const float* __restrict__ h, const float* __restrict__ kpts,
    __half* __restrict__ agg)
{
    __shared__ float s_infl[AGG_PTS][32][KPN];
    __shared__ int   s_idx[AGG_PTS][32];
    __shared__ float s_rel[AGG_PTS][32][3];
    __shared__ float s_kp[KPN][3];
    __shared__ int   s_cnt[AGG_PTS];

    int cl = blockIdx.y;
    const float* coords = cl ? c1 : c0;
    int p0 = blockIdx.x * AGG_PTS;
    int tid = threadIdx.x;
    size_t qbase = (size_t)cl * NP + p0;

    if (tid < KPN * 3) s_kp[tid / 3][tid % 3] = kpts[tid];
    if (tid < AGG_PTS) s_cnt[tid] = cntArr[qbase + tid];
#pragma unroll
    for (int s = 0; s < 2; s++) {
        int i = tid + s * 256;
        int pt = i >> 5, k = i & 31;
        s_idx[pt][k] = idx[(qbase + pt) * 32 + k];
    }
    __syncthreads();

#pragma unroll
    for (int s = 0; s < 2; s++) {
        int i = tid + s * 256;
        int pt = i >> 5, k = i & 31;
        int j = s_idx[pt][k], n = p0 + pt;
        s_rel[pt][k][0] = __fsub_rn(coords[3 * j],     coords[3 * n]);
        s_rel[pt][k][1] = __fsub_rn(coords[3 * j + 1], coords[3 * n + 1]);
        s_rel[pt][k][2] = __fsub_rn(coords[3 * j + 2], coords[3 * n + 2]);
    }
    __syncthreads();

#pragma unroll
    for (int s = 0; s < 2; s++) {
        int i = tid + s * 256;
        int pt = i >> 5, k = i & 31;
        float rx = s_rel[pt][k][0], ry = s_rel[pt][k][1], rz = s_rel[pt][k][2];
        bool valid = k < s_cnt[pt];
#pragma unroll
        for (int p = 0; p < KPN; p++) {
            float dx = rx - s_kp[p][0];
            float dy = ry - s_kp[p][1];
            float dz = rz - s_kp[p][2];
            float dist = sqrtf(dx * dx + dy * dy + dz * dz);
            float w = fmaxf(1.0f - dist * (1.0f / 0.096f), 0.0f);
            s_infl[pt][k][p] = valid ? w : 0.0f;
        }
    }
    __syncthreads();

    int pt = tid >> 4;
    int c4 = (tid & 15) << 2;
    const float* hcl = h + (size_t)cl * NP * SCC;

    float acc[KPN][4];
#pragma unroll
    for (int p = 0; p < KPN; p++)
#pragma unroll
        for (int d = 0; d < 4; d++) acc[p][d] = 0.f;

    float4 hv = *reinterpret_cast<const float4*>(&hcl[(size_t)s_idx[pt][0] * SCC + c4]);
#pragma unroll
    for (int k = 0; k < 32; k++) {
        float4 nxt;
        if (k < 31)
            nxt = *reinterpret_cast<const float4*>(&hcl[(size_t)s_idx[pt][k + 1] * SCC + c4]);
#pragma unroll
        for (int p = 0; p < KPN; p++) {
            float w = s_infl[pt][k][p];
            acc[p][0] += w * hv.x; acc[p][1] += w * hv.y;
            acc[p][2] += w * hv.z; acc[p][3] += w * hv.w;
        }
        hv = nxt;
    }

    __half* o = agg + (qbase + pt) * KDIM + c4;
#pragma unroll
    for (int p = 0; p < KPN; p++) {
        __half2 h01 = __floats2half2_rn(acc[p][0], acc[p][1]);
        __half2 h23 = __floats2half2_rn(acc[p][2], acc[p][3]);
        uint2 pk;
        pk.x = *reinterpret_cast<unsigned int*>(&h01);
        pk.y = *reinterpret_cast<unsigned int*>(&h23);
        *reinterpret_cast<uint2*>(&o[p * SCC]) = pk;
    }
}

// ---------------- batch norm finalize + apply ----------------
__global__ __launch_bounds__(256) void bn_final(const float* __restrict__ part,
                                                float* __restrict__ mu,
                                                float* __restrict__ rstd)
{
    int cl = blockIdx.x, ch = threadIdx.x;
    float s = 0.f, s2 = 0.f;
    for (int r = 0; r < 64; r++) {
        s  += part[((size_t)(cl * 2 + 0) * 64 + r) * OUTC + ch];
        s2 += part[((size_t)(cl * 2 + 1) * 64 + r) * OUTC + ch];
    }
    float m = s * (1.0f / 8192.0f);
    float v = s2 * (1.0f / 8192.0f) - m * m;
    v = v < 0.f ? 0.f : v;
    mu[cl * OUTC + ch]   = m;
    rstd[cl * OUTC + ch] = rsqrtf(v + 1e-5f);
}

__global__ __launch_bounds__(256) void bn_apply(float* __restrict__ y,
                                                const float* __restrict__ mu,
                                                const float* __restrict__ rstd,
                                                const float* __restrict__ gamma,
                                                const float* __restrict__ beta)
{
    size_t i = (size_t)blockIdx.x * blockDim.x + threadIdx.x;
    int ch = (int)(i & (OUTC - 1));
    int cl = (int)(i >> 21);
    float v = y[i];
    float t = gamma[ch] * (v - mu[cl * OUTC + ch]) * rstd[cl * OUTC + ch] + beta[ch];
    y[i] = t > 0.f ? t : 0.1f * t;
}

// ---------------- launch ----------------
extern "C" void kernel_launch(void* const* d_in, const int* in_sizes, int n_in,
                              void* d_out, int out_size)
{
    const float* src    = (const float*)d_in[0];
    const float* tgt    = (const float*)d_in[1];
    const float* src_c  = (const float*)d_in[2];
    const float* tgt_c  = (const float*)d_in[3];
    const float* W_in   = (const float*)d_in[4];
    const float* b_in   = (const float*)d_in[5];
    const float* kpts   = (const float*)d_in[6];
    const float* W_kp   = (const float*)d_in[7];
    const float* W_out  = (const float*)d_in[8];
    const float* b_out  = (const float*)d_in[9];
    const float* gamma  = (const float*)d_in[10];
    const float* beta   = (const float*)d_in[11];
    float* out = (float*)d_out;

    void* p;
    cudaGetSymbolAddress(&p, g_h);        float*  hP    = (float*)p;
    cudaGetSymbolAddress(&p, g_idx);      int*    idxP  = (int*)p;
    cudaGetSymbolAddress(&p, g_cnt);      int*    cntP  = (int*)p;
    cudaGetSymbolAddress(&p, g_agg);      __half* aggP  = (__half*)p;
    cudaGetSymbolAddress(&p, g_wt);       __half* wtP   = (__half*)p;
    cudaGetSymbolAddress(&p, g_h2);       float*  h2P   = (float*)p;
    cudaGetSymbolAddress(&p, g_part);     float*  partP = (float*)p;
    cudaGetSymbolAddress(&p, g_mu);       float*  muP   = (float*)p;
    cudaGetSymbolAddress(&p, g_rstd);     float*  rstdP = (float*)p;
    cudaGetSymbolAddress(&p, g_cellcnt);  int*    ccntP = (int*)p;
    cudaGetSymbolAddress(&p, g_fill);     int*    fillP = (int*)p;
    cudaGetSymbolAddress(&p, g_cellstart);int*    cstP  = (int*)p;
    cudaGetSymbolAddress(&p, g_sorted);   float4* srtP  = (float4*)p;

    const int KNN_SMEM = KNN_TPB * 33 * 8;   // 16896 B
    cudaFuncSetAttribute(knn_grid, cudaFuncAttributeMaxDynamicSharedMemorySize, KNN_SMEM);
    cudaFuncSetAttribute(gemm_k, cudaFuncAttributeMaxDynamicSharedMemorySize, GEMM_SMEM);

    // --- spatial grid build + weight conversion ---
    cudaMemsetAsync(ccntP, 0, 2 * 512 * sizeof(int));
    cudaMemsetAsync(fillP, 0, 2 * 512 * sizeof(int));
    grid_hist<<<64, 256>>>(src_c, tgt_c, ccntP);
    wconv<<<KDIM * SCC / 256, 256>>>(W_kp, wtP);
    grid_scan<<<2, 512>>>(ccntP, cstP);
    grid_scatter<<<64, 256>>>(src_c, tgt_c, cstP, fillP, srtP);

    // 1) h = x @ W_in + b_in
    gemm_k<<<dim3(1, 64, 2), 256, GEMM_SMEM>>>(src, tgt, W_in, b_in, hP,
                                               NP, SCC, INC, (size_t)NP * SCC, nullptr);

    // 2) grid-accelerated radius-filtered top-32
    knn_grid<<<dim3(NP / KNN_TPB, 2), KNN_TPB, KNN_SMEM>>>(src_c, tgt_c, cstP, srtP,
                                                           idxP, cntP);

    // 3) KPConv influence-weighted aggregation -> agg [N, 960] (fp16)
    agg_kernel<<<dim3(NP / AGG_PTS, 2), 256>>>(src_c, tgt_c, idxP, cntP, hP, kpts, aggP);

    // 4) h2 = agg @ W_kp  (HMMA fp16 x fp16 -> fp32)
    gemm_hmma<<<dim3(NP / 128, 2), 256>>>(aggP, wtP, h2P);

    // 5) y = h2 @ W_out + b_out -> d_out, with fused BN partial sums
    gemm_k<<<dim3(4, 64, 2), 256, GEMM_SMEM>>>(h2P, h2P + (size_t)NP * SCC, W_out, b_out,
                                               out, NP, OUTC, SCC, (size_t)NP * OUTC, partP);

    // 6) batch norm finalize + apply (in place on d_out)
    bn_final<<<2, 256>>>(partP, muP, rstdP);
    bn_apply<<<(2 * NP * OUTC) / 256, 256>>>(out, muP, rstdP, gamma, beta);

    // 7) coords pass-through
    cudaMemcpyAsync(out + (size_t)2 * NP * OUTC, src_c, NP * 3 * sizeof(float),
                    cudaMemcpyDeviceToDevice);
    cudaMemcpyAsync(out + (size_t)2 * NP * OUTC + NP * 3, tgt_c, NP * 3 * sizeof(float),
                    cudaMemcpyDeviceToDevice);
}

// round 9
// speedup vs baseline: 1.3692x; 1.0125x over previous
#include <cuda_runtime.h>
#include <cuda_fp16.h>
#include <stdint.h>
#include <math.h>

#define NP    8192
#define INC   256
#define SCC   64
#define OUTC  256
#define KPN   15
#define KDIM  (KPN * SCC)     // 960
#define AGG_PTS 16
#define KNN_TPB 64

// ---------------- scratch (__device__ globals, no allocations) ----------------
__device__ __align__(256) float  g_h   [2 * NP * SCC];                 // 4 MB
__device__ __align__(256) int    g_idx [2 * NP * 32];                  // 2 MB
__device__ __align__(256) int    g_cnt [2 * NP];
__device__ __align__(256) __half g_agg [(size_t)2 * NP * KDIM];        // 30 MB (fp16)
__device__ __align__(256) __half g_wt  [SCC * KDIM];                   // W_kp^T fp16 [64][960]
__device__ __align__(256) __half g_wt2 [OUTC * SCC];                   // W_out^T fp16 [256][64]
__device__ __align__(256) __half g_h2  [2 * NP * SCC];                 // 2 MB fp16
__device__ __align__(256) float  g_part[2 * 2 * 64 * OUTC];
__device__ __align__(256) float  g_mu  [2 * OUTC];
__device__ __align__(256) float  g_rstd[2 * OUTC];
__device__ __align__(256) int    g_cellstart[2 * 513];
__device__ __align__(256) float4 g_sorted   [2 * NP];   // xyz + original index (bits)

// ---------------- 128x64 tiled fp32 GEMM, double-buffered (used for gemm1) ----------------
#define GEMM_SMEM (2 * (32 * 132 + 32 * 64) * 4)   // 50176 B dynamic

__global__ __launch_bounds__(256) void gemm_k(
    const float* __restrict__ A0, const float* __restrict__ A1,
    const float* __restrict__ B,  const float* __restrict__ bias,
    float* __restrict__ C, int M, int N, int K, size_t strideC)
{
    extern __shared__ float smem_g[];
    float (*As)[32][132] = (float (*)[32][132])smem_g;
    float (*Bs)[32][64]  = (float (*)[32][64])(smem_g + 2 * 32 * 132);

    const float* A = blockIdx.z ? A1 : A0;
    float* Cp = C + (size_t)blockIdx.z * strideC;

    int tid = threadIdx.x;
    int tx = tid & 15;
    int ty = tid >> 4;
    int row0 = blockIdx.y * 128, col0 = blockIdx.x * 64;

    float acc[8][4];
#pragma unroll
    for (int m = 0; m < 8; m++)
#pragma unroll
        for (int n = 0; n < 4; n++) acc[m][n] = 0.f;

    float4 a_reg[4], b_reg[2];
    int ar[4], ac[4], br[2], bc[2];
#pragma unroll
    for (int pass = 0; pass < 4; pass++) {
        int idx = tid + pass * 256;
        ar[pass] = idx >> 3; ac[pass] = (idx & 7) * 4;
    }
#pragma unroll
    for (int pass = 0; pass < 2; pass++) {
        int idx = tid + pass * 256;
        br[pass] = idx >> 4; bc[pass] = (idx & 15) * 4;
    }

    const int KT = K >> 5;

#pragma unroll
    for (int pass = 0; pass < 4; pass++)
        a_reg[pass] = *reinterpret_cast<const float4*>(&A[(size_t)(row0 + ar[pass]) * K + ac[pass]]);
#pragma unroll
    for (int pass = 0; pass < 2; pass++)
        b_reg[pass] = *reinterpret_cast<const float4*>(&B[(size_t)br[pass] * N + col0 + bc[pass]]);
#pragma unroll
    for (int pass = 0; pass < 4; pass++) {
        As[0][ac[pass] + 0][ar[pass]] = a_reg[pass].x;
        As[0][ac[pass] + 1][ar[pass]] = a_reg[pass].y;
        As[0][ac[pass] + 2][ar[pass]] = a_reg[pass].z;
        As[0][ac[pass] + 3][ar[pass]] = a_reg[pass].w;
    }
#pragma unroll
    for (int pass = 0; pass < 2; pass++)
        *reinterpret_cast<float4*>(&Bs[0][br[pass]][bc[pass]]) = b_reg[pass];
    __syncthreads();

    for (int kt = 0; kt < KT; kt++) {
        int cur = kt & 1;
        int k0n = (kt + 1) << 5;
        if (kt + 1 < KT) {
#pragma unroll
            for (int pass = 0; pass < 4; pass++)
                a_reg[pass] = *reinterpret_cast<const float4*>(
                    &A[(size_t)(row0 + ar[pass]) * K + k0n + ac[pass]]);
#pragma unroll
            for (int pass = 0; pass < 2; pass++)
                b_reg[pass] = *reinterpret_cast<const float4*>(
                    &B[(size_t)(k0n + br[pass]) * N + col0 + bc[pass]]);
        }
#pragma unroll
        for (int k = 0; k < 32; k++) {
            float4 a0 = *reinterpret_cast<const float4*>(&As[cur][k][ty * 8]);
            float4 a1 = *reinterpret_cast<const float4*>(&As[cur][k][ty * 8 + 4]);
            float4 b  = *reinterpret_cast<const float4*>(&Bs[cur][k][tx * 4]);
            acc[0][0] += a0.x * b.x; acc[0][1] += a0.x * b.y; acc[0][2] += a0.x * b.z; acc[0][3] += a0.x * b.w;
            acc[1][0] += a0.y * b.x; acc[1][1] += a0.y * b.y; acc[1][2] += a0.y * b.z; acc[1][3] += a0.y * b.w;
            acc[2][0] += a0.z * b.x; acc[2][1] += a0.z * b.y; acc[2][2] += a0.z * b.z; acc[2][3] += a0.z * b.w;
            acc[3][0] += a0.w * b.x; acc[3][1] += a0.w * b.y; acc[3][2] += a0.w * b.z; acc[3][3] += a0.w * b.w;
            acc[4][0] += a1.x * b.x; acc[4][1] += a1.x * b.y; acc[4][2] += a1.x * b.z; acc[4][3] += a1.x * b.w;
            acc[5][0] += a1.y * b.x; acc[5][1] += a1.y * b.y; acc[5][2] += a1.y * b.z; acc[5][3] += a1.y * b.w;
            acc[6][0] += a1.z * b.x; acc[6][1] += a1.z * b.y; acc[6][2] += a1.z * b.z; acc[6][3] += a1.z * b.w;
            acc[7][0] += a1.w * b.x; acc[7][1] += a1.w * b.y; acc[7][2] += a1.w * b.z; acc[7][3] += a1.w * b.w;
        }
        if (kt + 1 < KT) {
            int nxt = (kt + 1) & 1;
#pragma unroll
            for (int pass = 0; pass < 4; pass++) {
                As[nxt][ac[pass] + 0][ar[pass]] = a_reg[pass].x;
                As[nxt][ac[pass] + 1][ar[pass]] = a_reg[pass].y;
                As[nxt][ac[pass] + 2][ar[pass]] = a_reg[pass].z;
                As[nxt][ac[pass] + 3][ar[pass]] = a_reg[pass].w;
            }
#pragma unroll
            for (int pass = 0; pass < 2; pass++)
                *reinterpret_cast<float4*>(&Bs[nxt][br[pass]][bc[pass]]) = b_reg[pass];
            __syncthreads();
        }
    }

    float bv0 = 0.f, bv1 = 0.f, bv2 = 0.f, bv3 = 0.f;
    if (bias) {
        bv0 = bias[col0 + tx * 4 + 0];
        bv1 = bias[col0 + tx * 4 + 1];
        bv2 = bias[col0 + tx * 4 + 2];
        bv3 = bias[col0 + tx * 4 + 3];
    }
#pragma unroll
    for (int m = 0; m < 8; m++) {
        float4 v;
        v.x = acc[m][0] + bv0; v.y = acc[m][1] + bv1;
        v.z = acc[m][2] + bv2; v.w = acc[m][3] + bv3;
        *reinterpret_cast<float4*>(&Cp[(size_t)(row0 + ty * 8 + m) * N + col0 + tx * 4]) = v;
    }
}

// ---------------- combined grid build + weight conversions (one launch) ----------------
__device__ __forceinline__ int cell_of(float x, float y, float z) {
    int cx = (int)(x * 8.0f); cx = cx < 0 ? 0 : (cx > 7 ? 7 : cx);
    int cy = (int)(y * 8.0f); cy = cy < 0 ? 0 : (cy > 7 ? 7 : cy);
    int cz = (int)(z * 8.0f); cz = cz < 0 ? 0 : (cz > 7 ? 7 : cz);
    return (cz * 8 + cy) * 8 + cx;
}

#define BUILD_BLOCKS 18

__global__ __launch_bounds__(512) void grid_build(
    const float* __restrict__ c0, const float* __restrict__ c1,
    const float* __restrict__ Wkp, const float* __restrict__ Wout,
    __half* __restrict__ wt, __half* __restrict__ wt2,
    int* __restrict__ start, float4* __restrict__ sorted)
{
    int b = blockIdx.x;
    int t = threadIdx.x;
    if (b < 2) {
        __shared__ short s_cell[NP];    // 16 KB
        __shared__ int s_cnt[512], s_sc[512], s_fill[512];
        const float* c = b ? c1 : c0;
        s_cnt[t] = 0; s_fill[t] = 0;
        __syncthreads();
#pragma unroll
        for (int i = 0; i < 16; i++) {
            int p = t + i * 512;
            int cell = cell_of(c[3 * p], c[3 * p + 1], c[3 * p + 2]);
            s_cell[p] = (short)cell;
            atomicAdd(&s_cnt[cell], 1);
        }
        __syncthreads();
        s_sc[t] = s_cnt[t];
        __syncthreads();
#pragma unroll
        for (int off = 1; off < 512; off <<= 1) {
            int v = (t >= off) ? s_sc[t - off] : 0;
            __syncthreads();
            s_sc[t] += v;
            __syncthreads();
        }
        start[b * 513 + t + 1] = s_sc[t];
        if (t == 0) start[b * 513] = 0;
        __syncthreads();
#pragma unroll
        for (int i = 0; i < 16; i++) {
            int p = t + i * 512;
            int cell = s_cell[p];
            int pos = s_sc[cell] - s_cnt[cell] + atomicAdd(&s_fill[cell], 1);
            sorted[b * NP + pos] = make_float4(c[3 * p], c[3 * p + 1], c[3 * p + 2],
                                               __int_as_float(p));
        }
    } else {
        int gt = (b - 2) * 512 + t;
        int stride = (BUILD_BLOCKS - 2) * 512;
        for (int i = gt; i < KDIM * SCC; i += stride) {
            int k = i >> 6, n = i & 63;
            wt[n * KDIM + k] = __float2half_rn(Wkp[i]);
        }
        for (int i = gt; i < SCC * OUTC; i += stride) {
            int k = i >> 8, n = i & 255;
            wt2[n * SCC + k] = __float2half_rn(Wout[i]);
        }
    }
}

// ---------------- kNN via grid: streaming radius-filtered top-32 ----------------
__global__ __launch_bounds__(KNN_TPB) void knn_grid(
    const float* __restrict__ c0, const float* __restrict__ c1,
    const int* __restrict__ start, const float4* __restrict__ sorted,
    int* __restrict__ out_idx, int* __restrict__ out_cnt)
{
    extern __shared__ char smraw[];
    float* smd = (float*)smraw;
    int*   smi = (int*)(smraw + KNN_TPB * 33 * 4);

    int cl = blockIdx.y;
    const float* coords = cl ? c1 : c0;
    int tid = threadIdx.x;
    int q = blockIdx.x * KNN_TPB + tid;

    float qx = coords[3 * q], qy = coords[3 * q + 1], qz = coords[3 * q + 2];
    const float R2 = 0.0144f;

    int cx = (int)(qx * 8.0f); cx = cx < 0 ? 0 : (cx > 7 ? 7 : cx);
    int cy = (int)(qy * 8.0f); cy = cy < 0 ? 0 : (cy > 7 ? 7 : cy);
    int cz = (int)(qz * 8.0f); cz = cz < 0 ? 0 : (cz > 7 ? 7 : cz);
    int xlo = cx > 0 ? cx - 1 : 0, xhi = cx < 7 ? cx + 1 : 7;
    int ylo = cy > 0 ? cy - 1 : 0, yhi = cy < 7 ? cy + 1 : 7;
    int zlo = cz > 0 ? cz - 1 : 0, zhi = cz < 7 ? cz + 1 : 7;

    float* md = smd + tid * 33;
    int*   mi = smi + tid * 33;
    int keep = 0;
    float cm = 0.f; int ca = 0;
    const int* st = start + cl * 513;
    const float4* srt = sorted + (size_t)cl * NP;

    for (int z = zlo; z <= zhi; z++)
        for (int y = ylo; y <= yhi; y++) {
            int rowcell = (z * 8 + y) * 8;
            int jb = st[rowcell + xlo];
            int je = st[rowcell + xhi + 1];
#pragma unroll 4
            for (int j = jb; j < je; j++) {
                float4 pc = srt[j];
                float dx = __fsub_rn(qx, pc.x);
                float dy = __fsub_rn(qy, pc.y);
                float dz = __fsub_rn(qz, pc.z);
                float d2 = __fadd_rn(__fadd_rn(__fmul_rn(dx, dx), __fmul_rn(dy, dy)),
                                     __fmul_rn(dz, dz));
                if (d2 <= R2) {
                    if (keep < 32) {
                        md[keep] = d2; mi[keep] = __float_as_int(pc.w); keep++;
                        if (keep == 32) {
                            cm = md[0]; ca = 0;
#pragma unroll
                            for (int s = 1; s < 32; s++) { float v = md[s]; if (v > cm) { cm = v; ca = s; } }
                        }
                    } else if (d2 < cm) {
                        md[ca] = d2; mi[ca] = __float_as_int(pc.w);
                        cm = md[0]; ca = 0;
#pragma unroll
                        for (int s = 1; s < 32; s++) { float v = md[s]; if (v > cm) { cm = v; ca = s; } }
                    }
                }
            }
        }

    int* oi = out_idx + ((size_t)cl * NP + q) * 32;
    for (int s = 0; s < 32; s++) oi[s] = (s < keep) ? mi[s] : 0;
    out_cnt[cl * NP + q] = keep;
}

// ---------------- KPConv aggregate (register-resident, 16 pts/block, fp16 out) ----------------
__global__ __launch_bounds__(256) void agg_kernel(
    const float* __restrict__ c0, const float* __restrict__ c1,
    const int* __restrict__ idx, const int* __restrict__ cntArr,
    const float* __restrict__ h, const float* __restrict__ kpts,
    __half* __restrict__ agg)
{
    __shared__ float s_infl[AGG_PTS][32][KPN];
    __shared__ int   s_idx[AGG_PTS][32];
    __shared__ float s_rel[AGG_PTS][32][3];
    __shared__ float s_kp[KPN][3];
    __shared__ int   s_cnt[AGG_PTS];

    int cl = blockIdx.y;
    const float* coords = cl ? c1 : c0;
    int p0 = blockIdx.x * AGG_PTS;
    int tid = threadIdx.x;
    size_t qbase = (size_t)cl * NP + p0;

    if (tid < KPN * 3) s_kp[tid / 3][tid % 3] = kpts[tid];
    if (tid < AGG_PTS) s_cnt[tid] = cntArr[qbase + tid];
#pragma unroll
    for (int s = 0; s < 2; s++) {
        int i = tid + s * 256;
        int pt = i >> 5, k = i & 31;
        s_idx[pt][k] = idx[(qbase + pt) * 32 + k];
    }
    __syncthreads();

#pragma unroll
    for (int s = 0; s < 2; s++) {
        int i = tid + s * 256;
        int pt = i >> 5, k = i & 31;
        int j = s_idx[pt][k], n = p0 + pt;
        s_rel[pt][k][0] = __fsub_rn(coords[3 * j],     coords[3 * n]);
        s_rel[pt][k][1] = __fsub_rn(coords[3 * j + 1], coords[3 * n + 1]);
        s_rel[pt][k][2] = __fsub_rn(coords[3 * j + 2], coords[3 * n + 2]);
    }
    __syncthreads();

#pragma unroll
    for (int s = 0; s < 2; s++) {
        int i = tid + s * 256;
        int pt = i >> 5, k = i & 31;
        float rx = s_rel[pt][k][0], ry = s_rel[pt][k][1], rz = s_rel[pt][k][2];
        bool valid = k < s_cnt[pt];
#pragma unroll
        for (int p = 0; p < KPN; p++) {
            float dx = rx - s_kp[p][0];
            float dy = ry - s_kp[p][1];
            float dz = rz - s_kp[p][2];
            float dist = sqrtf(dx * dx + dy * dy + dz * dz);
            float w = fmaxf(1.0f - dist * (1.0f / 0.096f), 0.0f);
            s_infl[pt][k][p] = valid ? w : 0.0f;
        }
    }
    __syncthreads();

    int pt = tid >> 4;
    int c4 = (tid & 15) << 2;
    const float* hcl = h + (size_t)cl * NP * SCC;

    float acc[KPN][4];
#pragma unroll
    for (int p = 0; p < KPN; p++)
#pragma unroll
        for (int d = 0; d < 4; d++) acc[p][d] = 0.f;

    float4 hv = *reinterpret_cast<const float4*>(&hcl[(size_t)s_idx[pt][0] * SCC + c4]);
#pragma unroll
    for (int k = 0; k < 32; k++) {
        float4 nxt;
        if (k < 31)
            nxt = *reinterpret_cast<const float4*>(&hcl[(size_t)s_idx[pt][k + 1] * SCC + c4]);
#pragma unroll
        for (int p = 0; p < KPN; p++) {
            float w = s_infl[pt][k][p];
            acc[p][0] += w * hv.x; acc[p][1] += w * hv.y;
            acc[p][2] += w * hv.z; acc[p][3] += w * hv.w;
        }
        hv = nxt;
    }

    __half* o = agg + (qbase + pt) * KDIM + c4;
#pragma unroll
    for (int p = 0; p < KPN; p++) {
        __half2 h01 = __floats2half2_rn(acc[p][0], acc[p][1]);
        __half2 h23 = __floats2half2_rn(acc[p][2], acc[p][3]);
        uint2 pk;
        pk.x = *reinterpret_cast<unsigned int*>(&h01);
        pk.y = *reinterpret_cast<unsigned int*>(&h23);
        *reinterpret_cast<uint2*>(&o[p * SCC]) = pk;
    }
}

// ---------------- HMMA helpers ----------------
__device__ __forceinline__ void mma16816(float* c, const uint32_t* a, const uint32_t* b) {
    asm volatile(
        "mma.sync.aligned.m16n8k16.row.col.f32.f16.f16.f32 "
        "{%0,%1,%2,%3}, {%4,%5,%6,%7}, {%8,%9}, {%0,%1,%2,%3};\n"
        : "+f"(c[0]), "+f"(c[1]), "+f"(c[2]), "+f"(c[3])
        : "r"(a[0]), "r"(a[1]), "r"(a[2]), "r"(a[3]), "r"(b[0]), "r"(b[1]));
}

// ---------------- HMMA GEMM 1: h2(fp16) = agg[8192,960] @ Wkp[960,64] ----------------
__global__ __launch_bounds__(256) void gemm_hmma(
    const __half* __restrict__ A, const __half* __restrict__ Wt,
    __half* __restrict__ C)
{
    __shared__ __half As[128][40];
    __shared__ __half Bs[64][40];

    int cl = blockIdx.y;
    const __half* Ab = A + (size_t)cl * NP * KDIM;
    __half* Cb = C + (size_t)cl * NP * SCC;
    int row0 = blockIdx.x * 128;
    int tid = threadIdx.x, lane = tid & 31, warp = tid >> 5;
    int wm = warp >> 1, wn = warp & 1;
    int g = lane >> 2, tig = lane & 3;

    float acc[2][4][4];
#pragma unroll
    for (int am = 0; am < 2; am++)
#pragma unroll
        for (int an = 0; an < 4; an++)
#pragma unroll
            for (int d = 0; d < 4; d++) acc[am][an][d] = 0.f;

    for (int k0 = 0; k0 < KDIM; k0 += 32) {
#pragma unroll
        for (int s = 0; s < 2; s++) {
            int ch = tid + s * 256;
            int r = ch >> 2, k8 = (ch & 3) * 8;
            *reinterpret_cast<uint4*>(&As[r][k8]) =
                *reinterpret_cast<const uint4*>(&Ab[(size_t)(row0 + r) * KDIM + k0 + k8]);
        }
        {
            int n = tid >> 2, k8 = (tid & 3) * 8;
            *reinterpret_cast<uint4*>(&Bs[n][k8]) =
                *reinterpret_cast<const uint4*>(&Wt[(size_t)n * KDIM + k0 + k8]);
        }
        __syncthreads();

#pragma unroll
        for (int ks = 0; ks < 32; ks += 16) {
            uint32_t a[2][4], b[4][2];
#pragma unroll
            for (int am = 0; am < 2; am++) {
                int r = wm * 32 + am * 16 + g;
                a[am][0] = *reinterpret_cast<const uint32_t*>(&As[r][ks + tig * 2]);
                a[am][1] = *reinterpret_cast<const uint32_t*>(&As[r + 8][ks + tig * 2]);
                a[am][2] = *reinterpret_cast<const uint32_t*>(&As[r][ks + tig * 2 + 8]);
                a[am][3] = *reinterpret_cast<const uint32_t*>(&As[r + 8][ks + tig * 2 + 8]);
            }
#pragma unroll
            for (int an = 0; an < 4; an++) {
                int n = wn * 32 + an * 8 + g;
                b[an][0] = *reinterpret_cast<const uint32_t*>(&Bs[n][ks + tig * 2]);
                b[an][1] = *reinterpret_cast<const uint32_t*>(&Bs[n][ks + tig * 2 + 8]);
            }
#pragma unroll
            for (int am = 0; am < 2; am++)
#pragma unroll
                for (int an = 0; an < 4; an++)
                    mma16816(acc[am][an], a[am], b[an]);
        }
        __syncthreads();
    }

#pragma unroll
    for (int am = 0; am < 2; am++)
#pragma unroll
        for (int an = 0; an < 4; an++) {
            int r = row0 + wm * 32 + am * 16 + g;
            int c = wn * 32 + an * 8 + tig * 2;
            __half2 v0 = __floats2half2_rn(acc[am][an][0], acc[am][an][1]);
            __half2 v1 = __floats2half2_rn(acc[am][an][2], acc[am][an][3]);
            *reinterpret_cast<__half2*>(&Cb[(size_t)r * SCC + c]) = v0;
            *reinterpret_cast<__half2*>(&Cb[(size_t)(r + 8) * SCC + c]) = v1;
        }
}

// ---------------- HMMA GEMM 2: y = h2[8192,64] @ W_out[64,256] + b + BN partials ----------------
// Block: 128 rows x 128 cols, 8 warps (4x2), warp tile 32x64. K=64 single pass.
__global__ __launch_bounds__(256) void gemm_hmma2(
    const __half* __restrict__ A, const __half* __restrict__ Wt2,
    const float* __restrict__ bias, float* __restrict__ C,
    float* __restrict__ part)
{
    __shared__ __half As[128][72];
    __shared__ __half Bs[128][72];
    __shared__ float s_red[2][4][128];

    int cl = blockIdx.z;
    const __half* Ab = A + (size_t)cl * NP * SCC;
    float* Cb = C + (size_t)cl * NP * OUTC;
    int row0 = blockIdx.x * 128;
    int col0 = blockIdx.y * 128;
    int tid = threadIdx.x, lane = tid & 31, warp = tid >> 5;
    int wm = warp >> 1, wn = warp & 1;
    int g = lane >> 2, tig = lane & 3;

    // load A tile 128x64 and B tile 128x64 (8 uint4 per row)
#pragma unroll
    for (int s = 0; s < 4; s++) {
        int ch = tid + s * 256;
        int r = ch >> 3, k8 = (ch & 7) * 8;
        *reinterpret_cast<uint4*>(&As[r][k8]) =
            *reinterpret_cast<const uint4*>(&Ab[(size_t)(row0 + r) * SCC + k8]);
        *reinterpret_cast<uint4*>(&Bs[r][k8]) =
            *reinterpret_cast<const uint4*>(&Wt2[(size_t)(col0 + r) * SCC + k8]);
    }
    __syncthreads();

    float acc[2][8][4];
#pragma unroll
    for (int am = 0; am < 2; am++)
#pragma unroll
        for (int an = 0; an < 8; an++)
#pragma unroll
            for (int d = 0; d < 4; d++) acc[am][an][d] = 0.f;

#pragma unroll
    for (int ks = 0; ks < 64; ks += 16) {
        uint32_t a[2][4], b[8][2];
#pragma unroll
        for (int am = 0; am < 2; am++) {
            int r = wm * 32 + am * 16 + g;
            a[am][0] = *reinterpret_cast<const uint32_t*>(&As[r][ks + tig * 2]);
            a[am][1] = *reinterpret_cast<const uint32_t*>(&As[r + 8][ks + tig * 2]);
            a[am][2] = *reinterpret_cast<const uint32_t*>(&As[r][ks + tig * 2 + 8]);
            a[am][3] = *reinterpret_cast<const uint32_t*>(&As[r + 8][ks + tig * 2 + 8]);
        }
#pragma unroll
        for (int an = 0; an < 8; an++) {
            int n = wn * 64 + an * 8 + g;
            b[an][0] = *reinterpret_cast<const uint32_t*>(&Bs[n][ks + tig * 2]);
            b[an][1] = *reinterpret_cast<const uint32_t*>(&Bs[n][ks + tig * 2 + 8]);
        }
#pragma unroll
        for (int am = 0; am < 2; am++)
#pragma unroll
            for (int an = 0; an < 8; an++)
                mma16816(acc[am][an], a[am], b[an]);
    }

    // epilogue: bias, store C, BN partial sums
#pragma unroll
    for (int an = 0; an < 8; an++) {
        int c = wn * 64 + an * 8 + tig * 2;
        float bv0 = bias[col0 + c], bv1 = bias[col0 + c + 1];
        float s0 = 0.f, s1 = 0.f, q0 = 0.f, q1 = 0.f;
#pragma unroll
        for (int am = 0; am < 2; am++) {
            int r = row0 + wm * 32 + am * 16 + g;
            float v0 = acc[am][an][0] + bv0, v1 = acc[am][an][1] + bv1;
            float v2 = acc[am][an][2] + bv0, v3 = acc[am][an][3] + bv1;
            float2 w0; w0.x = v0; w0.y = v1;
            float2 w1; w1.x = v2; w1.y = v3;
            *reinterpret_cast<float2*>(&Cb[(size_t)r * OUTC + col0 + c]) = w0;
            *reinterpret_cast<float2*>(&Cb[(size_t)(r + 8) * OUTC + col0 + c]) = w1;
            s0 += v0 + v2; s1 += v1 + v3;
            q0 += v0 * v0 + v2 * v2; q1 += v1 * v1 + v3 * v3;
        }
        // reduce over the 8 g-lanes (same tig): lanes differ in bits 2..4
#pragma unroll
        for (int m = 4; m <= 16; m <<= 1) {
            s0 += __shfl_xor_sync(0xffffffffu, s0, m);
            s1 += __shfl_xor_sync(0xffffffffu, s1, m);
            q0 += __shfl_xor_sync(0xffffffffu, q0, m);
            q1 += __shfl_xor_sync(0xffffffffu, q1, m);
        }
        if (g == 0) {
            s_red[0][wm][c] = s0; s_red[0][wm][c + 1] = s1;
            s_red[1][wm][c] = q0; s_red[1][wm][c + 1] = q1;
        }
    }
    __syncthreads();
    {
        int c = tid & 127, s = tid >> 7;
        float v = s_red[s][0][c] + s_red[s][1][c] + s_red[s][2][c] + s_red[s][3][c];
        part[((size_t)(cl * 2 + s) * 64 + blockIdx.x) * OUTC + col0 + c] = v;
    }
}

// ---------------- batch norm finalize + apply ----------------
__global__ __launch_bounds__(256) void bn_final(const float* __restrict__ part,
                                                float* __restrict__ mu,
                                                float* __restrict__ rstd)
{
    int cl = blockIdx.x, ch = threadIdx.x;
    float s = 0.f, s2 = 0.f;
    for (int r = 0; r < 64; r++) {
        s  += part[((size_t)(cl * 2 + 0) * 64 + r) * OUTC + ch];
        s2 += part[((size_t)(cl * 2 + 1) * 64 + r) * OUTC + ch];
    }
    float m = s * (1.0f / 8192.0f);
    float v = s2 * (1.0f / 8192.0f) - m * m;
    v = v < 0.f ? 0.f : v;
    mu[cl * OUTC + ch]   = m;
    rstd[cl * OUTC + ch] = rsqrtf(v + 1e-5f);
}

__global__ __launch_bounds__(256) void bn_apply(float* __restrict__ y,
                                                const float* __restrict__ mu,
                                                const float* __restrict__ rstd,
                                                const float* __restrict__ gamma,
                                                const float* __restrict__ beta)
{
    size_t i4 = (size_t)blockIdx.x * blockDim.x + threadIdx.x;   // float4 index
    size_t base = i4 * 4;
    int ch = (int)(base & (OUTC - 1));
    int cl = (int)(base >> 21);
    float4 v = *reinterpret_cast<float4*>(&y[base]);
    const float* muc = mu + cl * OUTC + ch;
    const float* rsc = rstd + cl * OUTC + ch;
    const float* gc = gamma + ch;
    const float* bc = beta + ch;
    float t0 = gc[0] * (v.x - muc[0]) * rsc[0] + bc[0];
    float t1 = gc[1] * (v.y - muc[1]) * rsc[1] + bc[1];
    float t2 = gc[2] * (v.z - muc[2]) * rsc[2] + bc[2];
    float t3 = gc[3] * (v.w - muc[3]) * rsc[3] + bc[3];
    v.x = t0 > 0.f ? t0 : 0.1f * t0;
    v.y = t1 > 0.f ? t1 : 0.1f * t1;
    v.z = t2 > 0.f ? t2 : 0.1f * t2;
    v.w = t3 > 0.f ? t3 : 0.1f * t3;
    *reinterpret_cast<float4*>(&y[base]) = v;
}

// ---------------- launch ----------------
extern "C" void kernel_launch(void* const* d_in, const int* in_sizes, int n_in,
                              void* d_out, int out_size)
{
    const float* src    = (const float*)d_in[0];
    const float* tgt    = (const float*)d_in[1];
    const float* src_c  = (const float*)d_in[2];
    const float* tgt_c  = (const float*)d_in[3];
    const float* W_in   = (const float*)d_in[4];
    const float* b_in   = (const float*)d_in[5];
    const float* kpts   = (const float*)d_in[6];
    const float* W_kp   = (const float*)d_in[7];
    const float* W_out  = (const float*)d_in[8];
    const float* b_out  = (const float*)d_in[9];
    const float* gamma  = (const float*)d_in[10];
    const float* beta   = (const float*)d_in[11];
    float* out = (float*)d_out;

    void* p;
    cudaGetSymbolAddress(&p, g_h);        float*  hP    = (float*)p;
    cudaGetSymbolAddress(&p, g_idx);      int*    idxP  = (int*)p;
    cudaGetSymbolAddress(&p, g_cnt);      int*    cntP  = (int*)p;
    cudaGetSymbolAddress(&p, g_agg);      __half* aggP  = (__half*)p;
    cudaGetSymbolAddress(&p, g_wt);       __half* wtP   = (__half*)p;
    cudaGetSymbolAddress(&p, g_wt2);      __half* wt2P  = (__half*)p;
    cudaGetSymbolAddress(&p, g_h2);       __half* h2P   = (__half*)p;
    cudaGetSymbolAddress(&p, g_part);     float*  partP = (float*)p;
    cudaGetSymbolAddress(&p, g_mu);       float*  muP   = (float*)p;
    cudaGetSymbolAddress(&p, g_rstd);     float*  rstdP = (float*)p;
    cudaGetSymbolAddress(&p, g_cellstart);int*    cstP  = (int*)p;
    cudaGetSymbolAddress(&p, g_sorted);   float4* srtP  = (float4*)p;

    const int KNN_SMEM = KNN_TPB * 33 * 8;   // 16896 B
    cudaFuncSetAttribute(knn_grid, cudaFuncAttributeMaxDynamicSharedMemorySize, KNN_SMEM);
    cudaFuncSetAttribute(gemm_k, cudaFuncAttributeMaxDynamicSharedMemorySize, GEMM_SMEM);

    // 0) grid build + weight conversions (single launch)
    grid_build<<<BUILD_BLOCKS, 512>>>(src_c, tgt_c, W_kp, W_out, wtP, wt2P, cstP, srtP);

    // 1) h = x @ W_in + b_in
    gemm_k<<<dim3(1, 64, 2), 256, GEMM_SMEM>>>(src, tgt, W_in, b_in, hP,
                                               NP, SCC, INC, (size_t)NP * SCC);

    // 2) grid-accelerated radius-filtered top-32
    knn_grid<<<dim3(NP / KNN_TPB, 2), KNN_TPB, KNN_SMEM>>>(src_c, tgt_c, cstP, srtP,
                                                           idxP, cntP);

    // 3) KPConv influence-weighted aggregation -> agg [N, 960] (fp16)
    agg_kernel<<<dim3(NP / AGG_PTS, 2), 256>>>(src_c, tgt_c, idxP, cntP, hP, kpts, aggP);

    // 4) h2(fp16) = agg @ W_kp  (HMMA)
    gemm_hmma<<<dim3(NP / 128, 2), 256>>>(aggP, wtP, h2P);

    // 5) y = h2 @ W_out + b_out -> d_out (HMMA) with fused BN partials
    gemm_hmma2<<<dim3(NP / 128, 2, 2), 256>>>(h2P, wt2P, b_out, out, partP);

    // 6) batch norm finalize + apply (in place on d_out)
    bn_final<<<2, 256>>>(partP, muP, rstdP);
    bn_apply<<<(2 * NP * OUTC / 4) / 256, 256>>>(out, muP, rstdP, gamma, beta);

    // 7) coords pass-through
    cudaMemcpyAsync(out + (size_t)2 * NP * OUTC, src_c, NP * 3 * sizeof(float),
                    cudaMemcpyDeviceToDevice);
    cudaMemcpyAsync(out + (size_t)2 * NP * OUTC + NP * 3, tgt_c, NP * 3 * sizeof(float),
                    cudaMemcpyDeviceToDevice);
}

// round 10
// speedup vs baseline: 1.8808x; 1.3736x over previous
#include <cuda_runtime.h>
#include <cuda_fp16.h>
#include <stdint.h>
#include <math.h>

#define NP    8192
#define INC   256
#define SCC   64
#define OUTC  256
#define KPN   15
#define KDIM  (KPN * SCC)     // 960
#define AGG_PTS 16
#define KNN_TPB 64

// ---------------- scratch (__device__ globals, no allocations) ----------------
__device__ __align__(256) float  g_h   [2 * NP * SCC];                 // 4 MB
__device__ __align__(256) int    g_idx [2 * NP * 32];                  // 2 MB
__device__ __align__(256) int    g_cnt [2 * NP];
__device__ __align__(256) __half g_agg [(size_t)2 * NP * KDIM];        // 30 MB (fp16)
__device__ __align__(256) __half g_wt  [SCC * KDIM];                   // W_kp^T fp16 [64][960]
__device__ __align__(256) __half g_wt2 [OUTC * SCC];                   // W_out^T fp16 [256][64]
__device__ __align__(256) __half g_h2  [2 * NP * SCC];                 // 2 MB fp16
__device__ __align__(256) float  g_part[2 * 2 * 64 * OUTC];
__device__ __align__(256) float  g_mu  [2 * OUTC];
__device__ __align__(256) float  g_rstd[2 * OUTC];
__device__ __align__(256) int    g_cellstart[2 * 513];
__device__ __align__(256) float4 g_sorted   [2 * NP];   // xyz + original index (bits)

// ---------------- 128x64 tiled fp32 GEMM, double-buffered (used for gemm1) ----------------
#define GEMM_SMEM (2 * (32 * 132 + 32 * 64) * 4)   // 50176 B dynamic

__global__ __launch_bounds__(256) void gemm_k(
    const float* __restrict__ A0, const float* __restrict__ A1,
    const float* __restrict__ B,  const float* __restrict__ bias,
    float* __restrict__ C, int M, int N, int K, size_t strideC)
{
    extern __shared__ float smem_g[];
    float (*As)[32][132] = (float (*)[32][132])smem_g;
    float (*Bs)[32][64]  = (float (*)[32][64])(smem_g + 2 * 32 * 132);

    const float* A = blockIdx.z ? A1 : A0;
    float* Cp = C + (size_t)blockIdx.z * strideC;

    int tid = threadIdx.x;
    int tx = tid & 15;
    int ty = tid >> 4;
    int row0 = blockIdx.y * 128, col0 = blockIdx.x * 64;

    float acc[8][4];
#pragma unroll
    for (int m = 0; m < 8; m++)
#pragma unroll
        for (int n = 0; n < 4; n++) acc[m][n] = 0.f;

    float4 a_reg[4], b_reg[2];
    int ar[4], ac[4], br[2], bc[2];
#pragma unroll
    for (int pass = 0; pass < 4; pass++) {
        int idx = tid + pass * 256;
        ar[pass] = idx >> 3; ac[pass] = (idx & 7) * 4;
    }
#pragma unroll
    for (int pass = 0; pass < 2; pass++) {
        int idx = tid + pass * 256;
        br[pass] = idx >> 4; bc[pass] = (idx & 15) * 4;
    }

    const int KT = K >> 5;

#pragma unroll
    for (int pass = 0; pass < 4; pass++)
        a_reg[pass] = *reinterpret_cast<const float4*>(&A[(size_t)(row0 + ar[pass]) * K + ac[pass]]);
#pragma unroll
    for (int pass = 0; pass < 2; pass++)
        b_reg[pass] = *reinterpret_cast<const float4*>(&B[(size_t)br[pass] * N + col0 + bc[pass]]);
#pragma unroll
    for (int pass = 0; pass < 4; pass++) {
        As[0][ac[pass] + 0][ar[pass]] = a_reg[pass].x;
        As[0][ac[pass] + 1][ar[pass]] = a_reg[pass].y;
        As[0][ac[pass] + 2][ar[pass]] = a_reg[pass].z;
        As[0][ac[pass] + 3][ar[pass]] = a_reg[pass].w;
    }
#pragma unroll
    for (int pass = 0; pass < 2; pass++)
        *reinterpret_cast<float4*>(&Bs[0][br[pass]][bc[pass]]) = b_reg[pass];
    __syncthreads();

    for (int kt = 0; kt < KT; kt++) {
        int cur = kt & 1;
        int k0n = (kt + 1) << 5;
        if (kt + 1 < KT) {
#pragma unroll
            for (int pass = 0; pass < 4; pass++)
                a_reg[pass] = *reinterpret_cast<const float4*>(
                    &A[(size_t)(row0 + ar[pass]) * K + k0n + ac[pass]]);
#pragma unroll
            for (int pass = 0; pass < 2; pass++)
                b_reg[pass] = *reinterpret_cast<const float4*>(
                    &B[(size_t)(k0n + br[pass]) * N + col0 + bc[pass]]);
        }
#pragma unroll
        for (int k = 0; k < 32; k++) {
            float4 a0 = *reinterpret_cast<const float4*>(&As[cur][k][ty * 8]);
            float4 a1 = *reinterpret_cast<const float4*>(&As[cur][k][ty * 8 + 4]);
            float4 b  = *reinterpret_cast<const float4*>(&Bs[cur][k][tx * 4]);
            acc[0][0] += a0.x * b.x; acc[0][1] += a0.x * b.y; acc[0][2] += a0.x * b.z; acc[0][3] += a0.x * b.w;
            acc[1][0] += a0.y * b.x; acc[1][1] += a0.y * b.y; acc[1][2] += a0.y * b.z; acc[1][3] += a0.y * b.w;
            acc[2][0] += a0.z * b.x; acc[2][1] += a0.z * b.y; acc[2][2] += a0.z * b.z; acc[2][3] += a0.z * b.w;
            acc[3][0] += a0.w * b.x; acc[3][1] += a0.w * b.y; acc[3][2] += a0.w * b.z; acc[3][3] += a0.w * b.w;
            acc[4][0] += a1.x * b.x; acc[4][1] += a1.x * b.y; acc[4][2] += a1.x * b.z; acc[4][3] += a1.x * b.w;
            acc[5][0] += a1.y * b.x; acc[5][1] += a1.y * b.y; acc[5][2] += a1.y * b.z; acc[5][3] += a1.y * b.w;
            acc[6][0] += a1.z * b.x; acc[6][1] += a1.z * b.y; acc[6][2] += a1.z * b.z; acc[6][3] += a1.z * b.w;
            acc[7][0] += a1.w * b.x; acc[7][1] += a1.w * b.y; acc[7][2] += a1.w * b.z; acc[7][3] += a1.w * b.w;
        }
        if (kt + 1 < KT) {
            int nxt = (kt + 1) & 1;
#pragma unroll
            for (int pass = 0; pass < 4; pass++) {
                As[nxt][ac[pass] + 0][ar[pass]] = a_reg[pass].x;
                As[nxt][ac[pass] + 1][ar[pass]] = a_reg[pass].y;
                As[nxt][ac[pass] + 2][ar[pass]] = a_reg[pass].z;
                As[nxt][ac[pass] + 3][ar[pass]] = a_reg[pass].w;
            }
#pragma unroll
            for (int pass = 0; pass < 2; pass++)
                *reinterpret_cast<float4*>(&Bs[nxt][br[pass]][bc[pass]]) = b_reg[pass];
            __syncthreads();
        }
    }

    float bv0 = 0.f, bv1 = 0.f, bv2 = 0.f, bv3 = 0.f;
    if (bias) {
        bv0 = bias[col0 + tx * 4 + 0];
        bv1 = bias[col0 + tx * 4 + 1];
        bv2 = bias[col0 + tx * 4 + 2];
        bv3 = bias[col0 + tx * 4 + 3];
    }
#pragma unroll
    for (int m = 0; m < 8; m++) {
        float4 v;
        v.x = acc[m][0] + bv0; v.y = acc[m][1] + bv1;
        v.z = acc[m][2] + bv2; v.w = acc[m][3] + bv3;
        *reinterpret_cast<float4*>(&Cp[(size_t)(row0 + ty * 8 + m) * N + col0 + tx * 4]) = v;
    }
}

// ---------------- combined grid build + weight conversions (one launch) ----------------
__device__ __forceinline__ int cell_of(float x, float y, float z) {
    int cx = (int)(x * 8.0f); cx = cx < 0 ? 0 : (cx > 7 ? 7 : cx);
    int cy = (int)(y * 8.0f); cy = cy < 0 ? 0 : (cy > 7 ? 7 : cy);
    int cz = (int)(z * 8.0f); cz = cz < 0 ? 0 : (cz > 7 ? 7 : cz);
    return (cz * 8 + cy) * 8 + cx;
}

#define BUILD_BLOCKS 18

__global__ __launch_bounds__(512) void grid_build(
    const float* __restrict__ c0, const float* __restrict__ c1,
    const float* __restrict__ Wkp, const float* __restrict__ Wout,
    __half* __restrict__ wt, __half* __restrict__ wt2,
    int* __restrict__ start, float4* __restrict__ sorted)
{
    int b = blockIdx.x;
    int t = threadIdx.x;
    if (b < 2) {
        __shared__ short s_cell[NP];    // 16 KB
        __shared__ int s_cnt[512], s_sc[512], s_fill[512];
        const float* c = b ? c1 : c0;
        s_cnt[t] = 0; s_fill[t] = 0;
        __syncthreads();
#pragma unroll
        for (int i = 0; i < 16; i++) {
            int p = t + i * 512;
            int cell = cell_of(c[3 * p], c[3 * p + 1], c[3 * p + 2]);
            s_cell[p] = (short)cell;
            atomicAdd(&s_cnt[cell], 1);
        }
        __syncthreads();
        s_sc[t] = s_cnt[t];
        __syncthreads();
#pragma unroll
        for (int off = 1; off < 512; off <<= 1) {
            int v = (t >= off) ? s_sc[t - off] : 0;
            __syncthreads();
            s_sc[t] += v;
            __syncthreads();
        }
        start[b * 513 + t + 1] = s_sc[t];
        if (t == 0) start[b * 513] = 0;
        __syncthreads();
#pragma unroll
        for (int i = 0; i < 16; i++) {
            int p = t + i * 512;
            int cell = s_cell[p];
            int pos = s_sc[cell] - s_cnt[cell] + atomicAdd(&s_fill[cell], 1);
            sorted[b * NP + pos] = make_float4(c[3 * p], c[3 * p + 1], c[3 * p + 2],
                                               __int_as_float(p));
        }
    } else {
        int gt = (b - 2) * 512 + t;
        int stride = (BUILD_BLOCKS - 2) * 512;
        for (int i = gt; i < KDIM * SCC; i += stride) {
            int k = i >> 6, n = i & 63;
            wt[n * KDIM + k] = __float2half_rn(Wkp[i]);
        }
        for (int i = gt; i < SCC * OUTC; i += stride) {
            int k = i >> 8, n = i & 255;
            wt2[n * SCC + k] = __float2half_rn(Wout[i]);
        }
    }
}

// ---------------- kNN via grid: SORTED query order ----------------
// Thread t of block b handles sorted position b*64+t: all lanes of a warp sit
// in the same / adjacent cells -> uniform loop bounds, broadcast L1 hits on the
// shared candidate stream. Results scatter to the original index. Distance math
// is bit-identical to the reference fp32 chain.
__global__ __launch_bounds__(KNN_TPB) void knn_grid(
    const int* __restrict__ start, const float4* __restrict__ sorted,
    int* __restrict__ out_idx, int* __restrict__ out_cnt)
{
    extern __shared__ char smraw[];
    float* smd = (float*)smraw;
    int*   smi = (int*)(smraw + KNN_TPB * 33 * 4);

    int cl = blockIdx.y;
    int tid = threadIdx.x;
    int s = blockIdx.x * KNN_TPB + tid;

    const int* st = start + cl * 513;
    const float4* srt = sorted + (size_t)cl * NP;

    float4 q4 = srt[s];
    float qx = q4.x, qy = q4.y, qz = q4.z;
    int orig = __float_as_int(q4.w);
    const float R2 = 0.0144f;

    int cx = (int)(qx * 8.0f); cx = cx < 0 ? 0 : (cx > 7 ? 7 : cx);
    int cy = (int)(qy * 8.0f); cy = cy < 0 ? 0 : (cy > 7 ? 7 : cy);
    int cz = (int)(qz * 8.0f); cz = cz < 0 ? 0 : (cz > 7 ? 7 : cz);
    int xlo = cx > 0 ? cx - 1 : 0, xhi = cx < 7 ? cx + 1 : 7;
    int ylo = cy > 0 ? cy - 1 : 0, yhi = cy < 7 ? cy + 1 : 7;
    int zlo = cz > 0 ? cz - 1 : 0, zhi = cz < 7 ? cz + 1 : 7;

    float* md = smd + tid * 33;
    int*   mi = smi + tid * 33;
    int keep = 0;
    float cm = 0.f; int ca = 0;

    for (int z = zlo; z <= zhi; z++)
        for (int y = ylo; y <= yhi; y++) {
            int rowcell = (z * 8 + y) * 8;
            int jb = st[rowcell + xlo];
            int je = st[rowcell + xhi + 1];
#pragma unroll 4
            for (int j = jb; j < je; j++) {
                float4 pc = srt[j];
                float dx = __fsub_rn(qx, pc.x);
                float dy = __fsub_rn(qy, pc.y);
                float dz = __fsub_rn(qz, pc.z);
                float d2 = __fadd_rn(__fadd_rn(__fmul_rn(dx, dx), __fmul_rn(dy, dy)),
                                     __fmul_rn(dz, dz));
                if (d2 <= R2) {
                    if (keep < 32) {
                        md[keep] = d2; mi[keep] = __float_as_int(pc.w); keep++;
                        if (keep == 32) {
                            cm = md[0]; ca = 0;
#pragma unroll
                            for (int u = 1; u < 32; u++) { float v = md[u]; if (v > cm) { cm = v; ca = u; } }
                        }
                    } else if (d2 < cm) {
                        md[ca] = d2; mi[ca] = __float_as_int(pc.w);
                        cm = md[0]; ca = 0;
#pragma unroll
                        for (int u = 1; u < 32; u++) { float v = md[u]; if (v > cm) { cm = v; ca = u; } }
                    }
                }
            }
        }

    int* oi = out_idx + ((size_t)cl * NP + orig) * 32;
    for (int u = 0; u < 32; u++) oi[u] = (u < keep) ? mi[u] : 0;
    out_cnt[cl * NP + orig] = keep;
}

// ---------------- KPConv aggregate (register-resident, 16 pts/block, fp16 out) ----------------
__global__ __launch_bounds__(256) void agg_kernel(
    const float* __restrict__ c0, const float* __restrict__ c1,
    const int* __restrict__ idx, const int* __restrict__ cntArr,
    const float* __restrict__ h, const float* __restrict__ kpts,
    __half* __restrict__ agg)
{
    __shared__ float s_infl[AGG_PTS][32][KPN];
    __shared__ int   s_idx[AGG_PTS][32];
    __shared__ float s_rel[AGG_PTS][32][3];
    __shared__ float s_kp[KPN][3];
    __shared__ int   s_cnt[AGG_PTS];

    int cl = blockIdx.y;
    const float* coords = cl ? c1 : c0;
    int p0 = blockIdx.x * AGG_PTS;
    int tid = threadIdx.x;
    size_t qbase = (size_t)cl * NP + p0;

    if (tid < KPN * 3) s_kp[tid / 3][tid % 3] = kpts[tid];
    if (tid < AGG_PTS) s_cnt[tid] = cntArr[qbase + tid];
#pragma unroll
    for (int s = 0; s < 2; s++) {
        int i = tid + s * 256;
        int pt = i >> 5, k = i & 31;
        s_idx[pt][k] = idx[(qbase + pt) * 32 + k];
    }
    __syncthreads();

#pragma unroll
    for (int s = 0; s < 2; s++) {
        int i = tid + s * 256;
        int pt = i >> 5, k = i & 31;
        int j = s_idx[pt][k], n = p0 + pt;
        s_rel[pt][k][0] = __fsub_rn(coords[3 * j],     coords[3 * n]);
        s_rel[pt][k][1] = __fsub_rn(coords[3 * j + 1], coords[3 * n + 1]);
        s_rel[pt][k][2] = __fsub_rn(coords[3 * j + 2], coords[3 * n + 2]);
    }
    __syncthreads();

#pragma unroll
    for (int s = 0; s < 2; s++) {
        int i = tid + s * 256;
        int pt = i >> 5, k = i & 31;
        float rx = s_rel[pt][k][0], ry = s_rel[pt][k][1], rz = s_rel[pt][k][2];
        bool valid = k < s_cnt[pt];
#pragma unroll
        for (int p = 0; p < KPN; p++) {
            float dx = rx - s_kp[p][0];
            float dy = ry - s_kp[p][1];
            float dz = rz - s_kp[p][2];
            float dist = sqrtf(dx * dx + dy * dy + dz * dz);
            float w = fmaxf(1.0f - dist * (1.0f / 0.096f), 0.0f);
            s_infl[pt][k][p] = valid ? w : 0.0f;
        }
    }
    __syncthreads();

    int pt = tid >> 4;
    int c4 = (tid & 15) << 2;
    const float* hcl = h + (size_t)cl * NP * SCC;

    float acc[KPN][4];
#pragma unroll
    for (int p = 0; p < KPN; p++)
#pragma unroll
        for (int d = 0; d < 4; d++) acc[p][d] = 0.f;

    float4 hv = *reinterpret_cast<const float4*>(&hcl[(size_t)s_idx[pt][0] * SCC + c4]);
#pragma unroll
    for (int k = 0; k < 32; k++) {
        float4 nxt;
        if (k < 31)
            nxt = *reinterpret_cast<const float4*>(&hcl[(size_t)s_idx[pt][k + 1] * SCC + c4]);
#pragma unroll
        for (int p = 0; p < KPN; p++) {
            float w = s_infl[pt][k][p];
            acc[p][0] += w * hv.x; acc[p][1] += w * hv.y;
            acc[p][2] += w * hv.z; acc[p][3] += w * hv.w;
        }
        hv = nxt;
    }

    __half* o = agg + (qbase + pt) * KDIM + c4;
#pragma unroll
    for (int p = 0; p < KPN; p++) {
        __half2 h01 = __floats2half2_rn(acc[p][0], acc[p][1]);
        __half2 h23 = __floats2half2_rn(acc[p][2], acc[p][3]);
        uint2 pk;
        pk.x = *reinterpret_cast<unsigned int*>(&h01);
        pk.y = *reinterpret_cast<unsigned int*>(&h23);
        *reinterpret_cast<uint2*>(&o[p * SCC]) = pk;
    }
}

// ---------------- HMMA helpers ----------------
__device__ __forceinline__ void mma16816(float* c, const uint32_t* a, const uint32_t* b) {
    asm volatile(
        "mma.sync.aligned.m16n8k16.row.col.f32.f16.f16.f32 "
        "{%0,%1,%2,%3}, {%4,%5,%6,%7}, {%8,%9}, {%0,%1,%2,%3};\n"
        : "+f"(c[0]), "+f"(c[1]), "+f"(c[2]), "+f"(c[3])
        : "r"(a[0]), "r"(a[1]), "r"(a[2]), "r"(a[3]), "r"(b[0]), "r"(b[1]));
}

// ---------------- HMMA GEMM 1: h2(fp16) = agg[8192,960] @ Wkp[960,64] ----------------
__global__ __launch_bounds__(256) void gemm_hmma(
    const __half* __restrict__ A, const __half* __restrict__ Wt,
    __half* __restrict__ C)
{
    __shared__ __half As[128][40];
    __shared__ __half Bs[64][40];

    int cl = blockIdx.y;
    const __half* Ab = A + (size_t)cl * NP * KDIM;
    __half* Cb = C + (size_t)cl * NP * SCC;
    int row0 = blockIdx.x * 128;
    int tid = threadIdx.x, lane = tid & 31, warp = tid >> 5;
    int wm = warp >> 1, wn = warp & 1;
    int g = lane >> 2, tig = lane & 3;

    float acc[2][4][4];
#pragma unroll
    for (int am = 0; am < 2; am++)
#pragma unroll
        for (int an = 0; an < 4; an++)
#pragma unroll
            for (int d = 0; d < 4; d++) acc[am][an][d] = 0.f;

    for (int k0 = 0; k0 < KDIM; k0 += 32) {
#pragma unroll
        for (int s = 0; s < 2; s++) {
            int ch = tid + s * 256;
            int r = ch >> 2, k8 = (ch & 3) * 8;
            *reinterpret_cast<uint4*>(&As[r][k8]) =
                *reinterpret_cast<const uint4*>(&Ab[(size_t)(row0 + r) * KDIM + k0 + k8]);
        }
        {
            int n = tid >> 2, k8 = (tid & 3) * 8;
            *reinterpret_cast<uint4*>(&Bs[n][k8]) =
                *reinterpret_cast<const uint4*>(&Wt[(size_t)n * KDIM + k0 + k8]);
        }
        __syncthreads();

#pragma unroll
        for (int ks = 0; ks < 32; ks += 16) {
            uint32_t a[2][4], b[4][2];
#pragma unroll
            for (int am = 0; am < 2; am++) {
                int r = wm * 32 + am * 16 + g;
                a[am][0] = *reinterpret_cast<const uint32_t*>(&As[r][ks + tig * 2]);
                a[am][1] = *reinterpret_cast<const uint32_t*>(&As[r + 8][ks + tig * 2]);
                a[am][2] = *reinterpret_cast<const uint32_t*>(&As[r][ks + tig * 2 + 8]);
                a[am][3] = *reinterpret_cast<const uint32_t*>(&As[r + 8][ks + tig * 2 + 8]);
            }
#pragma unroll
            for (int an = 0; an < 4; an++) {
                int n = wn * 32 + an * 8 + g;
                b[an][0] = *reinterpret_cast<const uint32_t*>(&Bs[n][ks + tig * 2]);
                b[an][1] = *reinterpret_cast<const uint32_t*>(&Bs[n][ks + tig * 2 + 8]);
            }
#pragma unroll
            for (int am = 0; am < 2; am++)
#pragma unroll
                for (int an = 0; an < 4; an++)
                    mma16816(acc[am][an], a[am], b[an]);
        }
        __syncthreads();
    }

#pragma unroll
    for (int am = 0; am < 2; am++)
#pragma unroll
        for (int an = 0; an < 4; an++) {
            int r = row0 + wm * 32 + am * 16 + g;
            int c = wn * 32 + an * 8 + tig * 2;
            __half2 v0 = __floats2half2_rn(acc[am][an][0], acc[am][an][1]);
            __half2 v1 = __floats2half2_rn(acc[am][an][2], acc[am][an][3]);
            *reinterpret_cast<__half2*>(&Cb[(size_t)r * SCC + c]) = v0;
            *reinterpret_cast<__half2*>(&Cb[(size_t)(r + 8) * SCC + c]) = v1;
        }
}

// ---------------- HMMA GEMM 2: y = h2[8192,64] @ W_out[64,256] + b + BN partials ----------------
__global__ __launch_bounds__(256) void gemm_hmma2(
    const __half* __restrict__ A, const __half* __restrict__ Wt2,
    const float* __restrict__ bias, float* __restrict__ C,
    float* __restrict__ part)
{
    __shared__ __half As[128][72];
    __shared__ __half Bs[128][72];
    __shared__ float s_red[2][4][128];

    int cl = blockIdx.z;
    const __half* Ab = A + (size_t)cl * NP * SCC;
    float* Cb = C + (size_t)cl * NP * OUTC;
    int row0 = blockIdx.x * 128;
    int col0 = blockIdx.y * 128;
    int tid = threadIdx.x, lane = tid & 31, warp = tid >> 5;
    int wm = warp >> 1, wn = warp & 1;
    int g = lane >> 2, tig = lane & 3;

#pragma unroll
    for (int s = 0; s < 4; s++) {
        int ch = tid + s * 256;
        int r = ch >> 3, k8 = (ch & 7) * 8;
        *reinterpret_cast<uint4*>(&As[r][k8]) =
            *reinterpret_cast<const uint4*>(&Ab[(size_t)(row0 + r) * SCC + k8]);
        *reinterpret_cast<uint4*>(&Bs[r][k8]) =
            *reinterpret_cast<const uint4*>(&Wt2[(size_t)(col0 + r) * SCC + k8]);
    }
    __syncthreads();

    float acc[2][8][4];
#pragma unroll
    for (int am = 0; am < 2; am++)
#pragma unroll
        for (int an = 0; an < 8; an++)
#pragma unroll
            for (int d = 0; d < 4; d++) acc[am][an][d] = 0.f;

#pragma unroll
    for (int ks = 0; ks < 64; ks += 16) {
        uint32_t a[2][4], b[8][2];
#pragma unroll
        for (int am = 0; am < 2; am++) {
            int r = wm * 32 + am * 16 + g;
            a[am][0] = *reinterpret_cast<const uint32_t*>(&As[r][ks + tig * 2]);
            a[am][1] = *reinterpret_cast<const uint32_t*>(&As[r + 8][ks + tig * 2]);
            a[am][2] = *reinterpret_cast<const uint32_t*>(&As[r][ks + tig * 2 + 8]);
            a[am][3] = *reinterpret_cast<const uint32_t*>(&As[r + 8][ks + tig * 2 + 8]);
        }
#pragma unroll
        for (int an = 0; an < 8; an++) {
            int n = wn * 64 + an * 8 + g;
            b[an][0] = *reinterpret_cast<const uint32_t*>(&Bs[n][ks + tig * 2]);
            b[an][1] = *reinterpret_cast<const uint32_t*>(&Bs[n][ks + tig * 2 + 8]);
        }
#pragma unroll
        for (int am = 0; am < 2; am++)
#pragma unroll
            for (int an = 0; an < 8; an++)
                mma16816(acc[am][an], a[am], b[an]);
    }

#pragma unroll
    for (int an = 0; an < 8; an++) {
        int c = wn * 64 + an * 8 + tig * 2;
        float bv0 = bias[col0 + c], bv1 = bias[col0 + c + 1];
        float s0 = 0.f, s1 = 0.f, q0 = 0.f, q1 = 0.f;
#pragma unroll
        for (int am = 0; am < 2; am++) {
            int r = row0 + wm * 32 + am * 16 + g;
            float v0 = acc[am][an][0] + bv0, v1 = acc[am][an][1] + bv1;
            float v2 = acc[am][an][2] + bv0, v3 = acc[am][an][3] + bv1;
            float2 w0; w0.x = v0; w0.y = v1;
            float2 w1; w1.x = v2; w1.y = v3;
            *reinterpret_cast<float2*>(&Cb[(size_t)r * OUTC + col0 + c]) = w0;
            *reinterpret_cast<float2*>(&Cb[(size_t)(r + 8) * OUTC + col0 + c]) = w1;
            s0 += v0 + v2; s1 += v1 + v3;
            q0 += v0 * v0 + v2 * v2; q1 += v1 * v1 + v3 * v3;
        }
#pragma unroll
        for (int m = 4; m <= 16; m <<= 1) {
            s0 += __shfl_xor_sync(0xffffffffu, s0, m);
            s1 += __shfl_xor_sync(0xffffffffu, s1, m);
            q0 += __shfl_xor_sync(0xffffffffu, q0, m);
            q1 += __shfl_xor_sync(0xffffffffu, q1, m);
        }
        if (g == 0) {
            s_red[0][wm][c] = s0; s_red[0][wm][c + 1] = s1;
            s_red[1][wm][c] = q0; s_red[1][wm][c + 1] = q1;
        }
    }
    __syncthreads();
    {
        int c = tid & 127, s = tid >> 7;
        float v = s_red[s][0][c] + s_red[s][1][c] + s_red[s][2][c] + s_red[s][3][c];
        part[((size_t)(cl * 2 + s) * 64 + blockIdx.x) * OUTC + col0 + c] = v;
    }
}

// ---------------- batch norm finalize + apply ----------------
__global__ __launch_bounds__(256) void bn_final(const float* __restrict__ part,
                                                float* __restrict__ mu,
                                                float* __restrict__ rstd)
{
    int cl = blockIdx.x, ch = threadIdx.x;
    float s = 0.f, s2 = 0.f;
    for (int r = 0; r < 64; r++) {
        s  += part[((size_t)(cl * 2 + 0) * 64 + r) * OUTC + ch];
        s2 += part[((size_t)(cl * 2 + 1) * 64 + r) * OUTC + ch];
    }
    float m = s * (1.0f / 8192.0f);
    float v = s2 * (1.0f / 8192.0f) - m * m;
    v = v < 0.f ? 0.f : v;
    mu[cl * OUTC + ch]   = m;
    rstd[cl * OUTC + ch] = rsqrtf(v + 1e-5f);
}

__global__ __launch_bounds__(256) void bn_apply(float* __restrict__ y,
                                                const float* __restrict__ mu,
                                                const float* __restrict__ rstd,
                                                const float* __restrict__ gamma,
                                                const float* __restrict__ beta)
{
    size_t i4 = (size_t)blockIdx.x * blockDim.x + threadIdx.x;
    size_t base = i4 * 4;
    int ch = (int)(base & (OUTC - 1));
    int cl = (int)(base >> 21);
    float4 v = *reinterpret_cast<float4*>(&y[base]);
    const float* muc = mu + cl * OUTC + ch;
    const float* rsc = rstd + cl * OUTC + ch;
    const float* gc = gamma + ch;
    const float* bc = beta + ch;
    float t0 = gc[0] * (v.x - muc[0]) * rsc[0] + bc[0];
    float t1 = gc[1] * (v.y - muc[1]) * rsc[1] + bc[1];
    float t2 = gc[2] * (v.z - muc[2]) * rsc[2] + bc[2];
    float t3 = gc[3] * (v.w - muc[3]) * rsc[3] + bc[3];
    v.x = t0 > 0.f ? t0 : 0.1f * t0;
    v.y = t1 > 0.f ? t1 : 0.1f * t1;
    v.z = t2 > 0.f ? t2 : 0.1f * t2;
    v.w = t3 > 0.f ? t3 : 0.1f * t3;
    *reinterpret_cast<float4*>(&y[base]) = v;
}

// ---------------- launch ----------------
extern "C" void kernel_launch(void* const* d_in, const int* in_sizes, int n_in,
                              void* d_out, int out_size)
{
    const float* src    = (const float*)d_in[0];
    const float* tgt    = (const float*)d_in[1];
    const float* src_c  = (const float*)d_in[2];
    const float* tgt_c  = (const float*)d_in[3];
    const float* W_in   = (const float*)d_in[4];
    const float* b_in   = (const float*)d_in[5];
    const float* kpts   = (const float*)d_in[6];
    const float* W_kp   = (const float*)d_in[7];
    const float* W_out  = (const float*)d_in[8];
    const float* b_out  = (const float*)d_in[9];
    const float* gamma  = (const float*)d_in[10];
    const float* beta   = (const float*)d_in[11];
    float* out = (float*)d_out;

    void* p;
    cudaGetSymbolAddress(&p, g_h);        float*  hP    = (float*)p;
    cudaGetSymbolAddress(&p, g_idx);      int*    idxP  = (int*)p;
    cudaGetSymbolAddress(&p, g_cnt);      int*    cntP  = (int*)p;
    cudaGetSymbolAddress(&p, g_agg);      __half* aggP  = (__half*)p;
    cudaGetSymbolAddress(&p, g_wt);       __half* wtP   = (__half*)p;
    cudaGetSymbolAddress(&p, g_wt2);      __half* wt2P  = (__half*)p;
    cudaGetSymbolAddress(&p, g_h2);       __half* h2P   = (__half*)p;
    cudaGetSymbolAddress(&p, g_part);     float*  partP = (float*)p;
    cudaGetSymbolAddress(&p, g_mu);       float*  muP   = (float*)p;
    cudaGetSymbolAddress(&p, g_rstd);     float*  rstdP = (float*)p;
    cudaGetSymbolAddress(&p, g_cellstart);int*    cstP  = (int*)p;
    cudaGetSymbolAddress(&p, g_sorted);   float4* srtP  = (float4*)p;

    const int KNN_SMEM = KNN_TPB * 33 * 8;   // 16896 B
    cudaFuncSetAttribute(knn_grid, cudaFuncAttributeMaxDynamicSharedMemorySize, KNN_SMEM);
    cudaFuncSetAttribute(gemm_k, cudaFuncAttributeMaxDynamicSharedMemorySize, GEMM_SMEM);

    // 0) grid build + weight conversions (single launch)
    grid_build<<<BUILD_BLOCKS, 512>>>(src_c, tgt_c, W_kp, W_out, wtP, wt2P, cstP, srtP);

    // 1) h = x @ W_in + b_in
    gemm_k<<<dim3(1, 64, 2), 256, GEMM_SMEM>>>(src, tgt, W_in, b_in, hP,
                                               NP, SCC, INC, (size_t)NP * SCC);

    // 2) grid kNN in SORTED query order
    knn_grid<<<dim3(NP / KNN_TPB, 2), KNN_TPB, KNN_SMEM>>>(cstP, srtP, idxP, cntP);

    // 3) KPConv influence-weighted aggregation -> agg [N, 960] (fp16)
    agg_kernel<<<dim3(NP / AGG_PTS, 2), 256>>>(src_c, tgt_c, idxP, cntP, hP, kpts, aggP);

    // 4) h2(fp16) = agg @ W_kp  (HMMA)
    gemm_hmma<<<dim3(NP / 128, 2), 256>>>(aggP, wtP, h2P);

    // 5) y = h2 @ W_out + b_out -> d_out (HMMA) with fused BN partials
    gemm_hmma2<<<dim3(NP / 128, 2, 2), 256>>>(h2P, wt2P, b_out, out, partP);

    // 6) batch norm finalize + apply (in place on d_out)
    bn_final<<<2, 256>>>(partP, muP, rstdP);
    bn_apply<<<(2 * NP * OUTC / 4) / 256, 256>>>(out, muP, rstdP, gamma, beta);

    // 7) coords pass-through
    cudaMemcpyAsync(out + (size_t)2 * NP * OUTC, src_c, NP * 3 * sizeof(float),
                    cudaMemcpyDeviceToDevice);
    cudaMemcpyAsync(out + (size_t)2 * NP * OUTC + NP * 3, tgt_c, NP * 3 * sizeof(float),
                    cudaMemcpyDeviceToDevice);
}

// round 11
// speedup vs baseline: 2.6709x; 1.4201x over previous
#include <cuda_runtime.h>
#include <cuda_fp16.h>
#include <stdint.h>
#include <math.h>

#define NP    8192
#define INC   256
#define SCC   64
#define OUTC  256
#define KPN   15
#define KDIM  (KPN * SCC)     // 960
#define AGG_PTS 16
#define KNN_TPB 128           // 32 queries/block x 4 lanes/query
#define KNN_QPB 32

// ---------------- scratch (__device__ globals, no allocations) ----------------
__device__ __align__(256) float  g_h   [2 * NP * SCC];                 // 4 MB
__device__ __align__(256) int    g_idx [2 * NP * 32];                  // 2 MB
__device__ __align__(256) int    g_cnt [2 * NP];
__device__ __align__(256) __half g_agg [(size_t)2 * NP * KDIM];        // 30 MB (fp16)
__device__ __align__(256) __half g_wt  [SCC * KDIM];                   // W_kp^T fp16 [64][960]
__device__ __align__(256) __half g_wt2 [OUTC * SCC];                   // W_out^T fp16 [256][64]
__device__ __align__(256) __half g_h2  [2 * NP * SCC];                 // 2 MB fp16
__device__ __align__(256) float  g_part[2 * 2 * 64 * OUTC];
__device__ __align__(256) float  g_mu  [2 * OUTC];
__device__ __align__(256) float  g_rstd[2 * OUTC];
__device__ __align__(256) int    g_cellstart[2 * 513];
__device__ __align__(256) float4 g_sorted   [2 * NP];   // xyz + original index (bits)

// ---------------- 128x64 tiled fp32 GEMM, double-buffered (used for gemm1) ----------------
#define GEMM_SMEM (2 * (32 * 132 + 32 * 64) * 4)   // 50176 B dynamic

__global__ __launch_bounds__(256) void gemm_k(
    const float* __restrict__ A0, const float* __restrict__ A1,
    const float* __restrict__ B,  const float* __restrict__ bias,
    float* __restrict__ C, int M, int N, int K, size_t strideC)
{
    extern __shared__ float smem_g[];
    float (*As)[32][132] = (float (*)[32][132])smem_g;
    float (*Bs)[32][64]  = (float (*)[32][64])(smem_g + 2 * 32 * 132);

    const float* A = blockIdx.z ? A1 : A0;
    float* Cp = C + (size_t)blockIdx.z * strideC;

    int tid = threadIdx.x;
    int tx = tid & 15;
    int ty = tid >> 4;
    int row0 = blockIdx.y * 128, col0 = blockIdx.x * 64;

    float acc[8][4];
#pragma unroll
    for (int m = 0; m < 8; m++)
#pragma unroll
        for (int n = 0; n < 4; n++) acc[m][n] = 0.f;

    float4 a_reg[4], b_reg[2];
    int ar[4], ac[4], br[2], bc[2];
#pragma unroll
    for (int pass = 0; pass < 4; pass++) {
        int idx = tid + pass * 256;
        ar[pass] = idx >> 3; ac[pass] = (idx & 7) * 4;
    }
#pragma unroll
    for (int pass = 0; pass < 2; pass++) {
        int idx = tid + pass * 256;
        br[pass] = idx >> 4; bc[pass] = (idx & 15) * 4;
    }

    const int KT = K >> 5;

#pragma unroll
    for (int pass = 0; pass < 4; pass++)
        a_reg[pass] = *reinterpret_cast<const float4*>(&A[(size_t)(row0 + ar[pass]) * K + ac[pass]]);
#pragma unroll
    for (int pass = 0; pass < 2; pass++)
        b_reg[pass] = *reinterpret_cast<const float4*>(&B[(size_t)br[pass] * N + col0 + bc[pass]]);
#pragma unroll
    for (int pass = 0; pass < 4; pass++) {
        As[0][ac[pass] + 0][ar[pass]] = a_reg[pass].x;
        As[0][ac[pass] + 1][ar[pass]] = a_reg[pass].y;
        As[0][ac[pass] + 2][ar[pass]] = a_reg[pass].z;
        As[0][ac[pass] + 3][ar[pass]] = a_reg[pass].w;
    }
#pragma unroll
    for (int pass = 0; pass < 2; pass++)
        *reinterpret_cast<float4*>(&Bs[0][br[pass]][bc[pass]]) = b_reg[pass];
    __syncthreads();

    for (int kt = 0; kt < KT; kt++) {
        int cur = kt & 1;
        int k0n = (kt + 1) << 5;
        if (kt + 1 < KT) {
#pragma unroll
            for (int pass = 0; pass < 4; pass++)
                a_reg[pass] = *reinterpret_cast<const float4*>(
                    &A[(size_t)(row0 + ar[pass]) * K + k0n + ac[pass]]);
#pragma unroll
            for (int pass = 0; pass < 2; pass++)
                b_reg[pass] = *reinterpret_cast<const float4*>(
                    &B[(size_t)(k0n + br[pass]) * N + col0 + bc[pass]]);
        }
#pragma unroll
        for (int k = 0; k < 32; k++) {
            float4 a0 = *reinterpret_cast<const float4*>(&As[cur][k][ty * 8]);
            float4 a1 = *reinterpret_cast<const float4*>(&As[cur][k][ty * 8 + 4]);
            float4 b  = *reinterpret_cast<const float4*>(&Bs[cur][k][tx * 4]);
            acc[0][0] += a0.x * b.x; acc[0][1] += a0.x * b.y; acc[0][2] += a0.x * b.z; acc[0][3] += a0.x * b.w;
            acc[1][0] += a0.y * b.x; acc[1][1] += a0.y * b.y; acc[1][2] += a0.y * b.z; acc[1][3] += a0.y * b.w;
            acc[2][0] += a0.z * b.x; acc[2][1] += a0.z * b.y; acc[2][2] += a0.z * b.z; acc[2][3] += a0.z * b.w;
            acc[3][0] += a0.w * b.x; acc[3][1] += a0.w * b.y; acc[3][2] += a0.w * b.z; acc[3][3] += a0.w * b.w;
            acc[4][0] += a1.x * b.x; acc[4][1] += a1.x * b.y; acc[4][2] += a1.x * b.z; acc[4][3] += a1.x * b.w;
            acc[5][0] += a1.y * b.x; acc[5][1] += a1.y * b.y; acc[5][2] += a1.y * b.z; acc[5][3] += a1.y * b.w;
            acc[6][0] += a1.z * b.x; acc[6][1] += a1.z * b.y; acc[6][2] += a1.z * b.z; acc[6][3] += a1.z * b.w;
            acc[7][0] += a1.w * b.x; acc[7][1] += a1.w * b.y; acc[7][2] += a1.w * b.z; acc[7][3] += a1.w * b.w;
        }
        if (kt + 1 < KT) {
            int nxt = (kt + 1) & 1;
#pragma unroll
            for (int pass = 0; pass < 4; pass++) {
                As[nxt][ac[pass] + 0][ar[pass]] = a_reg[pass].x;
                As[nxt][ac[pass] + 1][ar[pass]] = a_reg[pass].y;
                As[nxt][ac[pass] + 2][ar[pass]] = a_reg[pass].z;
                As[nxt][ac[pass] + 3][ar[pass]] = a_reg[pass].w;
            }
#pragma unroll
            for (int pass = 0; pass < 2; pass++)
                *reinterpret_cast<float4*>(&Bs[nxt][br[pass]][bc[pass]]) = b_reg[pass];
            __syncthreads();
        }
    }

    float bv0 = 0.f, bv1 = 0.f, bv2 = 0.f, bv3 = 0.f;
    if (bias) {
        bv0 = bias[col0 + tx * 4 + 0];
        bv1 = bias[col0 + tx * 4 + 1];
        bv2 = bias[col0 + tx * 4 + 2];
        bv3 = bias[col0 + tx * 4 + 3];
    }
#pragma unroll
    for (int m = 0; m < 8; m++) {
        float4 v;
        v.x = acc[m][0] + bv0; v.y = acc[m][1] + bv1;
        v.z = acc[m][2] + bv2; v.w = acc[m][3] + bv3;
        *reinterpret_cast<float4*>(&Cp[(size_t)(row0 + ty * 8 + m) * N + col0 + tx * 4]) = v;
    }
}

// ---------------- combined grid build + weight conversions (one launch) ----------------
__device__ __forceinline__ int cell_of(float x, float y, float z) {
    int cx = (int)(x * 8.0f); cx = cx < 0 ? 0 : (cx > 7 ? 7 : cx);
    int cy = (int)(y * 8.0f); cy = cy < 0 ? 0 : (cy > 7 ? 7 : cy);
    int cz = (int)(z * 8.0f); cz = cz < 0 ? 0 : (cz > 7 ? 7 : cz);
    return (cz * 8 + cy) * 8 + cx;
}

#define BUILD_BLOCKS 18

__global__ __launch_bounds__(512) void grid_build(
    const float* __restrict__ c0, const float* __restrict__ c1,
    const float* __restrict__ Wkp, const float* __restrict__ Wout,
    __half* __restrict__ wt, __half* __restrict__ wt2,
    int* __restrict__ start, float4* __restrict__ sorted)
{
    int b = blockIdx.x;
    int t = threadIdx.x;
    if (b < 2) {
        __shared__ short s_cell[NP];    // 16 KB
        __shared__ int s_cnt[512], s_sc[512], s_fill[512];
        const float* c = b ? c1 : c0;
        s_cnt[t] = 0; s_fill[t] = 0;
        __syncthreads();
#pragma unroll
        for (int i = 0; i < 16; i++) {
            int p = t + i * 512;
            int cell = cell_of(c[3 * p], c[3 * p + 1], c[3 * p + 2]);
            s_cell[p] = (short)cell;
            atomicAdd(&s_cnt[cell], 1);
        }
        __syncthreads();
        s_sc[t] = s_cnt[t];
        __syncthreads();
#pragma unroll
        for (int off = 1; off < 512; off <<= 1) {
            int v = (t >= off) ? s_sc[t - off] : 0;
            __syncthreads();
            s_sc[t] += v;
            __syncthreads();
        }
        start[b * 513 + t + 1] = s_sc[t];
        if (t == 0) start[b * 513] = 0;
        __syncthreads();
#pragma unroll
        for (int i = 0; i < 16; i++) {
            int p = t + i * 512;
            int cell = s_cell[p];
            int pos = s_sc[cell] - s_cnt[cell] + atomicAdd(&s_fill[cell], 1);
            sorted[b * NP + pos] = make_float4(c[3 * p], c[3 * p + 1], c[3 * p + 2],
                                               __int_as_float(p));
        }
    } else {
        int gt = (b - 2) * 512 + t;
        int stride = (BUILD_BLOCKS - 2) * 512;
        for (int i = gt; i < KDIM * SCC; i += stride) {
            int k = i >> 6, n = i & 63;
            wt[n * KDIM + k] = __float2half_rn(Wkp[i]);
        }
        for (int i = gt; i < SCC * OUTC; i += stride) {
            int k = i >> 8, n = i & 255;
            wt2[n * SCC + k] = __float2half_rn(Wout[i]);
        }
    }
}

// ---------------- kNN: sorted order, 4 lanes per query ----------------
// Lanes 4q..4q+3 split each cell-run with stride 4, each maintaining its own
// radius-filtered top-32 (per-lane top-32 of a subset is sufficient). Lane 0
// merges the quad's kept lists with the same deterministic stream-insert.
__global__ __launch_bounds__(KNN_TPB) void knn_grid(
    const int* __restrict__ start, const float4* __restrict__ sorted,
    int* __restrict__ out_idx, int* __restrict__ out_cnt)
{
    extern __shared__ char smraw[];
    float* smd = (float*)smraw;                          // [128][33]
    int*   smi = (int*)(smraw + KNN_TPB * 33 * 4);       // [128][33]
    int*   s_keep = (int*)(smraw + KNN_TPB * 33 * 8);    // [128]

    int cl = blockIdx.y;
    int tid = threadIdx.x;
    int lq = tid & 3;            // lane within quad
    int quad = tid >> 2;         // query slot 0..31
    int s = blockIdx.x * KNN_QPB + quad;

    const int* st = start + cl * 513;
    const float4* srt = sorted + (size_t)cl * NP;

    float4 q4 = srt[s];
    float qx = q4.x, qy = q4.y, qz = q4.z;
    int orig = __float_as_int(q4.w);
    const float R2 = 0.0144f;

    int cx = (int)(qx * 8.0f); cx = cx < 0 ? 0 : (cx > 7 ? 7 : cx);
    int cy = (int)(qy * 8.0f); cy = cy < 0 ? 0 : (cy > 7 ? 7 : cy);
    int cz = (int)(qz * 8.0f); cz = cz < 0 ? 0 : (cz > 7 ? 7 : cz);
    int xlo = cx > 0 ? cx - 1 : 0, xhi = cx < 7 ? cx + 1 : 7;
    int ylo = cy > 0 ? cy - 1 : 0, yhi = cy < 7 ? cy + 1 : 7;
    int zlo = cz > 0 ? cz - 1 : 0, zhi = cz < 7 ? cz + 1 : 7;

    float* md = smd + tid * 33;
    int*   mi = smi + tid * 33;
    int keep = 0;
    float cm = 0.f; int ca = 0;

    for (int z = zlo; z <= zhi; z++)
        for (int y = ylo; y <= yhi; y++) {
            int rowcell = (z * 8 + y) * 8;
            int jb = st[rowcell + xlo];
            int je = st[rowcell + xhi + 1];
#pragma unroll 2
            for (int j = jb + lq; j < je; j += 4) {
                float4 pc = srt[j];
                float dx = __fsub_rn(qx, pc.x);
                float dy = __fsub_rn(qy, pc.y);
                float dz = __fsub_rn(qz, pc.z);
                float d2 = __fadd_rn(__fadd_rn(__fmul_rn(dx, dx), __fmul_rn(dy, dy)),
                                     __fmul_rn(dz, dz));
                if (d2 <= R2) {
                    if (keep < 32) {
                        md[keep] = d2; mi[keep] = __float_as_int(pc.w); keep++;
                        if (keep == 32) {
                            cm = md[0]; ca = 0;
#pragma unroll
                            for (int u = 1; u < 32; u++) { float v = md[u]; if (v > cm) { cm = v; ca = u; } }
                        }
                    } else if (d2 < cm) {
                        md[ca] = d2; mi[ca] = __float_as_int(pc.w);
                        cm = md[0]; ca = 0;
#pragma unroll
                        for (int u = 1; u < 32; u++) { float v = md[u]; if (v > cm) { cm = v; ca = u; } }
                    }
                }
            }
        }

    s_keep[tid] = keep;
    __syncwarp();

    if (lq == 0) {
        // merge lanes 1..3 of this quad into lane 0's list
        for (int l = 1; l < 4; l++) {
            const float* od = smd + (tid + l) * 33;
            const int*   oi2 = smi + (tid + l) * 33;
            int oc = s_keep[tid + l];
            for (int e = 0; e < oc; e++) {
                float d2 = od[e];
                int ix = oi2[e];
                if (keep < 32) {
                    md[keep] = d2; mi[keep] = ix; keep++;
                    if (keep == 32) {
                        cm = md[0]; ca = 0;
#pragma unroll
                        for (int u = 1; u < 32; u++) { float v = md[u]; if (v > cm) { cm = v; ca = u; } }
                    }
                } else if (d2 < cm) {
                    md[ca] = d2; mi[ca] = ix;
                    cm = md[0]; ca = 0;
#pragma unroll
                    for (int u = 1; u < 32; u++) { float v = md[u]; if (v > cm) { cm = v; ca = u; } }
                }
            }
        }
        int* oi = out_idx + ((size_t)cl * NP + orig) * 32;
        for (int u = 0; u < 32; u++) oi[u] = (u < keep) ? mi[u] : 0;
        out_cnt[cl * NP + orig] = keep;
    }
}

// ---------------- KPConv aggregate (register-resident, 16 pts/block, fp16 out) ----------------
__global__ __launch_bounds__(256) void agg_kernel(
    const float* __restrict__ c0, const float* __restrict__ c1,
    const int* __restrict__ idx, const int* __restrict__ cntArr,
    const float* __restrict__ h, const float* __restrict__ kpts,
    __half* __restrict__ agg)
{
    __shared__ float s_infl[AGG_PTS][32][KPN];
    __shared__ int   s_idx[AGG_PTS][32];
    __shared__ float s_rel[AGG_PTS][32][3];
    __shared__ float s_kp[KPN][3];
    __shared__ int   s_cnt[AGG_PTS];

    int cl = blockIdx.y;
    const float* coords = cl ? c1 : c0;
    int p0 = blockIdx.x * AGG_PTS;
    int tid = threadIdx.x;
    size_t qbase = (size_t)cl * NP + p0;

    if (tid < KPN * 3) s_kp[tid / 3][tid % 3] = kpts[tid];
    if (tid < AGG_PTS) s_cnt[tid] = cntArr[qbase + tid];
#pragma unroll
    for (int s = 0; s < 2; s++) {
        int i = tid + s * 256;
        int pt = i >> 5, k = i & 31;
        s_idx[pt][k] = idx[(qbase + pt) * 32 + k];
    }
    __syncthreads();

#pragma unroll
    for (int s = 0; s < 2; s++) {
        int i = tid + s * 256;
        int pt = i >> 5, k = i & 31;
        int j = s_idx[pt][k], n = p0 + pt;
        s_rel[pt][k][0] = __fsub_rn(coords[3 * j],     coords[3 * n]);
        s_rel[pt][k][1] = __fsub_rn(coords[3 * j + 1], coords[3 * n + 1]);
        s_rel[pt][k][2] = __fsub_rn(coords[3 * j + 2], coords[3 * n + 2]);
    }
    __syncthreads();

#pragma unroll
    for (int s = 0; s < 2; s++) {
        int i = tid + s * 256;
        int pt = i >> 5, k = i & 31;
        float rx = s_rel[pt][k][0], ry = s_rel[pt][k][1], rz = s_rel[pt][k][2];
        bool valid = k < s_cnt[pt];
#pragma unroll
        for (int p = 0; p < KPN; p++) {
            float dx = rx - s_kp[p][0];
            float dy = ry - s_kp[p][1];
            float dz = rz - s_kp[p][2];
            float dist = sqrtf(dx * dx + dy * dy + dz * dz);
            float w = fmaxf(1.0f - dist * (1.0f / 0.096f), 0.0f);
            s_infl[pt][k][p] = valid ? w : 0.0f;
        }
    }
    __syncthreads();

    int pt = tid >> 4;
    int c4 = (tid & 15) << 2;
    const float* hcl = h + (size_t)cl * NP * SCC;

    float acc[KPN][4];
#pragma unroll
    for (int p = 0; p < KPN; p++)
#pragma unroll
        for (int d = 0; d < 4; d++) acc[p][d] = 0.f;

    float4 hv = *reinterpret_cast<const float4*>(&hcl[(size_t)s_idx[pt][0] * SCC + c4]);
#pragma unroll
    for (int k = 0; k < 32; k++) {
        float4 nxt;
        if (k < 31)
            nxt = *reinterpret_cast<const float4*>(&hcl[(size_t)s_idx[pt][k + 1] * SCC + c4]);
#pragma unroll
        for (int p = 0; p < KPN; p++) {
            float w = s_infl[pt][k][p];
            acc[p][0] += w * hv.x; acc[p][1] += w * hv.y;
            acc[p][2] += w * hv.z; acc[p][3] += w * hv.w;
        }
        hv = nxt;
    }

    __half* o = agg + (qbase + pt) * KDIM + c4;
#pragma unroll
    for (int p = 0; p < KPN; p++) {
        __half2 h01 = __floats2half2_rn(acc[p][0], acc[p][1]);
        __half2 h23 = __floats2half2_rn(acc[p][2], acc[p][3]);
        uint2 pk;
        pk.x = *reinterpret_cast<unsigned int*>(&h01);
        pk.y = *reinterpret_cast<unsigned int*>(&h23);
        *reinterpret_cast<uint2*>(&o[p * SCC]) = pk;
    }
}

// ---------------- HMMA helpers ----------------
__device__ __forceinline__ void mma16816(float* c, const uint32_t* a, const uint32_t* b) {
    asm volatile(
        "mma.sync.aligned.m16n8k16.row.col.f32.f16.f16.f32 "
        "{%0,%1,%2,%3}, {%4,%5,%6,%7}, {%8,%9}, {%0,%1,%2,%3};\n"
        : "+f"(c[0]), "+f"(c[1]), "+f"(c[2]), "+f"(c[3])
        : "r"(a[0]), "r"(a[1]), "r"(a[2]), "r"(a[3]), "r"(b[0]), "r"(b[1]));
}

// ---------------- HMMA GEMM 1: h2(fp16) = agg[8192,960] @ Wkp[960,64] ----------------
__global__ __launch_bounds__(256) void gemm_hmma(
    const __half* __restrict__ A, const __half* __restrict__ Wt,
    __half* __restrict__ C)
{
    __shared__ __half As[128][40];
    __shared__ __half Bs[64][40];

    int cl = blockIdx.y;
    const __half* Ab = A + (size_t)cl * NP * KDIM;
    __half* Cb = C + (size_t)cl * NP * SCC;
    int row0 = blockIdx.x * 128;
    int tid = threadIdx.x, lane = tid & 31, warp = tid >> 5;
    int wm = warp >> 1, wn = warp & 1;
    int g = lane >> 2, tig = lane & 3;

    float acc[2][4][4];
#pragma unroll
    for (int am = 0; am < 2; am++)
#pragma unroll
        for (int an = 0; an < 4; an++)
#pragma unroll
            for (int d = 0; d < 4; d++) acc[am][an][d] = 0.f;

    for (int k0 = 0; k0 < KDIM; k0 += 32) {
#pragma unroll
        for (int s = 0; s < 2; s++) {
            int ch = tid + s * 256;
            int r = ch >> 2, k8 = (ch & 3) * 8;
            *reinterpret_cast<uint4*>(&As[r][k8]) =
                *reinterpret_cast<const uint4*>(&Ab[(size_t)(row0 + r) * KDIM + k0 + k8]);
        }
        {
            int n = tid >> 2, k8 = (tid & 3) * 8;
            *reinterpret_cast<uint4*>(&Bs[n][k8]) =
                *reinterpret_cast<const uint4*>(&Wt[(size_t)n * KDIM + k0 + k8]);
        }
        __syncthreads();

#pragma unroll
        for (int ks = 0; ks < 32; ks += 16) {
            uint32_t a[2][4], b[4][2];
#pragma unroll
            for (int am = 0; am < 2; am++) {
                int r = wm * 32 + am * 16 + g;
                a[am][0] = *reinterpret_cast<const uint32_t*>(&As[r][ks + tig * 2]);
                a[am][1] = *reinterpret_cast<const uint32_t*>(&As[r + 8][ks + tig * 2]);
                a[am][2] = *reinterpret_cast<const uint32_t*>(&As[r][ks + tig * 2 + 8]);
                a[am][3] = *reinterpret_cast<const uint32_t*>(&As[r + 8][ks + tig * 2 + 8]);
            }
#pragma unroll
            for (int an = 0; an < 4; an++) {
                int n = wn * 32 + an * 8 + g;
                b[an][0] = *reinterpret_cast<const uint32_t*>(&Bs[n][ks + tig * 2]);
                b[an][1] = *reinterpret_cast<const uint32_t*>(&Bs[n][ks + tig * 2 + 8]);
            }
#pragma unroll
            for (int am = 0; am < 2; am++)
#pragma unroll
                for (int an = 0; an < 4; an++)
                    mma16816(acc[am][an], a[am], b[an]);
        }
        __syncthreads();
    }

#pragma unroll
    for (int am = 0; am < 2; am++)
#pragma unroll
        for (int an = 0; an < 4; an++) {
            int r = row0 + wm * 32 + am * 16 + g;
            int c = wn * 32 + an * 8 + tig * 2;
            __half2 v0 = __floats2half2_rn(acc[am][an][0], acc[am][an][1]);
            __half2 v1 = __floats2half2_rn(acc[am][an][2], acc[am][an][3]);
            *reinterpret_cast<__half2*>(&Cb[(size_t)r * SCC + c]) = v0;
            *reinterpret_cast<__half2*>(&Cb[(size_t)(r + 8) * SCC + c]) = v1;
        }
}

// ---------------- HMMA GEMM 2: y = h2[8192,64] @ W_out[64,256] + b + BN partials ----------------
__global__ __launch_bounds__(256) void gemm_hmma2(
    const __half* __restrict__ A, const __half* __restrict__ Wt2,
    const float* __restrict__ bias, float* __restrict__ C,
    float* __restrict__ part)
{
    __shared__ __half As[128][72];
    __shared__ __half Bs[128][72];
    __shared__ float s_red[2][4][128];

    int cl = blockIdx.z;
    const __half* Ab = A + (size_t)cl * NP * SCC;
    float* Cb = C + (size_t)cl * NP * OUTC;
    int row0 = blockIdx.x * 128;
    int col0 = blockIdx.y * 128;
    int tid = threadIdx.x, lane = tid & 31, warp = tid >> 5;
    int wm = warp >> 1, wn = warp & 1;
    int g = lane >> 2, tig = lane & 3;

#pragma unroll
    for (int s = 0; s < 4; s++) {
        int ch = tid + s * 256;
        int r = ch >> 3, k8 = (ch & 7) * 8;
        *reinterpret_cast<uint4*>(&As[r][k8]) =
            *reinterpret_cast<const uint4*>(&Ab[(size_t)(row0 + r) * SCC + k8]);
        *reinterpret_cast<uint4*>(&Bs[r][k8]) =
            *reinterpret_cast<const uint4*>(&Wt2[(size_t)(col0 + r) * SCC + k8]);
    }
    __syncthreads();

    float acc[2][8][4];
#pragma unroll
    for (int am = 0; am < 2; am++)
#pragma unroll
        for (int an = 0; an < 8; an++)
#pragma unroll
            for (int d = 0; d < 4; d++) acc[am][an][d] = 0.f;

#pragma unroll
    for (int ks = 0; ks < 64; ks += 16) {
        uint32_t a[2][4], b[8][2];
#pragma unroll
        for (int am = 0; am < 2; am++) {
            int r = wm * 32 + am * 16 + g;
            a[am][0] = *reinterpret_cast<const uint32_t*>(&As[r][ks + tig * 2]);
            a[am][1] = *reinterpret_cast<const uint32_t*>(&As[r + 8][ks + tig * 2]);
            a[am][2] = *reinterpret_cast<const uint32_t*>(&As[r][ks + tig * 2 + 8]);
            a[am][3] = *reinterpret_cast<const uint32_t*>(&As[r + 8][ks + tig * 2 + 8]);
        }
#pragma unroll
        for (int an = 0; an < 8; an++) {
            int n = wn * 64 + an * 8 + g;
            b[an][0] = *reinterpret_cast<const uint32_t*>(&Bs[n][ks + tig * 2]);
            b[an][1] = *reinterpret_cast<const uint32_t*>(&Bs[n][ks + tig * 2 + 8]);
        }
#pragma unroll
        for (int am = 0; am < 2; am++)
#pragma unroll
            for (int an = 0; an < 8; an++)
                mma16816(acc[am][an], a[am], b[an]);
    }

#pragma unroll
    for (int an = 0; an < 8; an++) {
        int c = wn * 64 + an * 8 + tig * 2;
        float bv0 = bias[col0 + c], bv1 = bias[col0 + c + 1];
        float s0 = 0.f, s1 = 0.f, q0 = 0.f, q1 = 0.f;
#pragma unroll
        for (int am = 0; am < 2; am++) {
            int r = row0 + wm * 32 + am * 16 + g;
            float v0 = acc[am][an][0] + bv0, v1 = acc[am][an][1] + bv1;
            float v2 = acc[am][an][2] + bv0, v3 = acc[am][an][3] + bv1;
            float2 w0; w0.x = v0; w0.y = v1;
            float2 w1; w1.x = v2; w1.y = v3;
            *reinterpret_cast<float2*>(&Cb[(size_t)r * OUTC + col0 + c]) = w0;
            *reinterpret_cast<float2*>(&Cb[(size_t)(r + 8) * OUTC + col0 + c]) = w1;
            s0 += v0 + v2; s1 += v1 + v3;
            q0 += v0 * v0 + v2 * v2; q1 += v1 * v1 + v3 * v3;
        }
#pragma unroll
        for (int m = 4; m <= 16; m <<= 1) {
            s0 += __shfl_xor_sync(0xffffffffu, s0, m);
            s1 += __shfl_xor_sync(0xffffffffu, s1, m);
            q0 += __shfl_xor_sync(0xffffffffu, q0, m);
            q1 += __shfl_xor_sync(0xffffffffu, q1, m);
        }
        if (g == 0) {
            s_red[0][wm][c] = s0; s_red[0][wm][c + 1] = s1;
            s_red[1][wm][c] = q0; s_red[1][wm][c + 1] = q1;
        }
    }
    __syncthreads();
    {
        int c = tid & 127, s = tid >> 7;
        float v = s_red[s][0][c] + s_red[s][1][c] + s_red[s][2][c] + s_red[s][3][c];
        part[((size_t)(cl * 2 + s) * 64 + blockIdx.x) * OUTC + col0 + c] = v;
    }
}

// ---------------- batch norm finalize + apply ----------------
__global__ __launch_bounds__(256) void bn_final(const float* __restrict__ part,
                                                float* __restrict__ mu,
                                                float* __restrict__ rstd)
{
    int cl = blockIdx.x, ch = threadIdx.x;
    float s = 0.f, s2 = 0.f;
    for (int r = 0; r < 64; r++) {
        s  += part[((size_t)(cl * 2 + 0) * 64 + r) * OUTC + ch];
        s2 += part[((size_t)(cl * 2 + 1) * 64 + r) * OUTC + ch];
    }
    float m = s * (1.0f / 8192.0f);
    float v = s2 * (1.0f / 8192.0f) - m * m;
    v = v < 0.f ? 0.f : v;
    mu[cl * OUTC + ch]   = m;
    rstd[cl * OUTC + ch] = rsqrtf(v + 1e-5f);
}

__global__ __launch_bounds__(256) void bn_apply(float* __restrict__ y,
                                                const float* __restrict__ mu,
                                                const float* __restrict__ rstd,
                                                const float* __restrict__ gamma,
                                                const float* __restrict__ beta)
{
    size_t i4 = (size_t)blockIdx.x * blockDim.x + threadIdx.x;
    size_t base = i4 * 4;
    int ch = (int)(base & (OUTC - 1));
    int cl = (int)(base >> 21);
    float4 v = *reinterpret_cast<float4*>(&y[base]);
    const float* muc = mu + cl * OUTC + ch;
    const float* rsc = rstd + cl * OUTC + ch;
    const float* gc = gamma + ch;
    const float* bc = beta + ch;
    float t0 = gc[0] * (v.x - muc[0]) * rsc[0] + bc[0];
    float t1 = gc[1] * (v.y - muc[1]) * rsc[1] + bc[1];
    float t2 = gc[2] * (v.z - muc[2]) * rsc[2] + bc[2];
    float t3 = gc[3] * (v.w - muc[3]) * rsc[3] + bc[3];
    v.x = t0 > 0.f ? t0 : 0.1f * t0;
    v.y = t1 > 0.f ? t1 : 0.1f * t1;
    v.z = t2 > 0.f ? t2 : 0.1f * t2;
    v.w = t3 > 0.f ? t3 : 0.1f * t3;
    *reinterpret_cast<float4*>(&y[base]) = v;
}

// ---------------- launch ----------------
extern "C" void kernel_launch(void* const* d_in, const int* in_sizes, int n_in,
                              void* d_out, int out_size)
{
    const float* src    = (const float*)d_in[0];
    const float* tgt    = (const float*)d_in[1];
    const float* src_c  = (const float*)d_in[2];
    const float* tgt_c  = (const float*)d_in[3];
    const float* W_in   = (const float*)d_in[4];
    const float* b_in   = (const float*)d_in[5];
    const float* kpts   = (const float*)d_in[6];
    const float* W_kp   = (const float*)d_in[7];
    const float* W_out  = (const float*)d_in[8];
    const float* b_out  = (const float*)d_in[9];
    const float* gamma  = (const float*)d_in[10];
    const float* beta   = (const float*)d_in[11];
    float* out = (float*)d_out;

    void* p;
    cudaGetSymbolAddress(&p, g_h);        float*  hP    = (float*)p;
    cudaGetSymbolAddress(&p, g_idx);      int*    idxP  = (int*)p;
    cudaGetSymbolAddress(&p, g_cnt);      int*    cntP  = (int*)p;
    cudaGetSymbolAddress(&p, g_agg);      __half* aggP  = (__half*)p;
    cudaGetSymbolAddress(&p, g_wt);       __half* wtP   = (__half*)p;
    cudaGetSymbolAddress(&p, g_wt2);      __half* wt2P  = (__half*)p;
    cudaGetSymbolAddress(&p, g_h2);       __half* h2P   = (__half*)p;
    cudaGetSymbolAddress(&p, g_part);     float*  partP = (float*)p;
    cudaGetSymbolAddress(&p, g_mu);       float*  muP   = (float*)p;
    cudaGetSymbolAddress(&p, g_rstd);     float*  rstdP = (float*)p;
    cudaGetSymbolAddress(&p, g_cellstart);int*    cstP  = (int*)p;
    cudaGetSymbolAddress(&p, g_sorted);   float4* srtP  = (float4*)p;

    const int KNN_SMEM = KNN_TPB * 33 * 8 + KNN_TPB * 4;   // 34304 B
    cudaFuncSetAttribute(knn_grid, cudaFuncAttributeMaxDynamicSharedMemorySize, KNN_SMEM);
    cudaFuncSetAttribute(gemm_k, cudaFuncAttributeMaxDynamicSharedMemorySize, GEMM_SMEM);

    // 0) grid build + weight conversions (single launch)
    grid_build<<<BUILD_BLOCKS, 512>>>(src_c, tgt_c, W_kp, W_out, wtP, wt2P, cstP, srtP);

    // 1) h = x @ W_in + b_in
    gemm_k<<<dim3(1, 64, 2), 256, GEMM_SMEM>>>(src, tgt, W_in, b_in, hP,
                                               NP, SCC, INC, (size_t)NP * SCC);

    // 2) grid kNN: sorted order, 4 lanes per query
    knn_grid<<<dim3(NP / KNN_QPB, 2), KNN_TPB, KNN_SMEM>>>(cstP, srtP, idxP, cntP);

    // 3) KPConv influence-weighted aggregation -> agg [N, 960] (fp16)
    agg_kernel<<<dim3(NP / AGG_PTS, 2), 256>>>(src_c, tgt_c, idxP, cntP, hP, kpts, aggP);

    // 4) h2(fp16) = agg @ W_kp  (HMMA)
    gemm_hmma<<<dim3(NP / 128, 2), 256>>>(aggP, wtP, h2P);

    // 5) y = h2 @ W_out + b_out -> d_out (HMMA) with fused BN partials
    gemm_hmma2<<<dim3(NP / 128, 2, 2), 256>>>(h2P, wt2P, b_out, out, partP);

    // 6) batch norm finalize + apply (in place on d_out)
    bn_final<<<2, 256>>>(partP, muP, rstdP);
    bn_apply<<<(2 * NP * OUTC / 4) / 256, 256>>>(out, muP, rstdP, gamma, beta);

    // 7) coords pass-through
    cudaMemcpyAsync(out + (size_t)2 * NP * OUTC, src_c, NP * 3 * sizeof(float),
                    cudaMemcpyDeviceToDevice);
    cudaMemcpyAsync(out + (size_t)2 * NP * OUTC + NP * 3, tgt_c, NP * 3 * sizeof(float),
                    cudaMemcpyDeviceToDevice);
}